// round 15
// baseline (speedup 1.0000x reference)
#include <cuda_runtime.h>
#include <cuda_bf16.h>
#include <cstdint>
#include <math.h>

#define SEQL   2048
#define BSZ    2
#define ROWS   (BSZ*SEQL)          // 4096
#define DIMX   2048
#define QLORA  1536
#define KVLORA 512
#define NHEADS 16
#define QKHD   192
#define NOPE_D 128
#define ROPE_D 64
#define VHD    128
#define QKVW   2112                // 1536 q + 512 kv_c + 64 k_pe
#define QSCALE 0.07216878364870323f

// ---------------- scratch (static device globals; no allocation) ----------------
__device__ float g_qkv[ROWS*QKVW];
__device__ float g_bqkv[QKVW];
__device__ float g_ropec[SEQL*32], g_ropes[SEQL*32];

__device__ __nv_bfloat16 g_xh  [ROWS*DIMX],   g_xl  [ROWS*DIMX];
__device__ __nv_bfloat16 g_qah [ROWS*QLORA],  g_qal [ROWS*QLORA];
__device__ __nv_bfloat16 g_kvch[ROWS*KVLORA], g_kvcl[ROWS*KVLORA];
__device__ __nv_bfloat16 g_atth[ROWS*2048],   g_attl[ROWS*2048];
__device__ __nv_bfloat16 g_wqkvh[QKVW*DIMX],  g_wqkvl[QKVW*DIMX];
__device__ __nv_bfloat16 g_wqbh[3072*QLORA],  g_wqbl[3072*QLORA];
__device__ __nv_bfloat16 g_wkvbh[4096*KVLORA],g_wkvbl[4096*KVLORA];
__device__ __nv_bfloat16 g_woh [DIMX*2048],   g_wol [DIMX*2048];
__device__ __nv_bfloat16 g_kfh[ROWS*NHEADS*QKHD], g_kfl[ROWS*NHEADS*QKHD];
__device__ __nv_bfloat16 g_vfh[ROWS*NHEADS*VHD],  g_vfl[ROWS*NHEADS*VHD];
__device__ __nv_bfloat16 g_qfh[ROWS*NHEADS*QKHD], g_qfl[ROWS*NHEADS*QKHD];

__device__ __forceinline__ uint32_t smem_to_u32(const void* p) {
    uint32_t a;
    asm("{ .reg .u64 t; cvta.to.shared.u64 t, %1; cvt.u32.u64 %0, t; }" : "=r"(a) : "l"(p));
    return a;
}
#define SWZ(x)   ((x) ^ (((x) >> 3) & 0x70))
#define SWZ64(x) ((x) ^ (((x) >> 3) & 0x30))

__device__ __forceinline__ void ldmatrix_x4(uint32_t* r, uint32_t addr) {
    asm volatile("ldmatrix.sync.aligned.m8n8.x4.shared.b16 {%0,%1,%2,%3}, [%4];"
        : "=r"(r[0]), "=r"(r[1]), "=r"(r[2]), "=r"(r[3]) : "r"(addr));
}
__device__ __forceinline__ void ldmatrix_x4_trans(uint32_t* r, uint32_t addr) {
    asm volatile("ldmatrix.sync.aligned.m8n8.x4.trans.shared.b16 {%0,%1,%2,%3}, [%4];"
        : "=r"(r[0]), "=r"(r[1]), "=r"(r[2]), "=r"(r[3]) : "r"(addr));
}
__device__ __forceinline__ void mma_bf16(float* c, const uint32_t* a, uint32_t b0, uint32_t b1) {
    asm volatile(
        "mma.sync.aligned.m16n8k16.row.col.f32.bf16.bf16.f32 "
        "{%0,%1,%2,%3}, {%4,%5,%6,%7}, {%8,%9}, {%0,%1,%2,%3};"
        : "+f"(c[0]), "+f"(c[1]), "+f"(c[2]), "+f"(c[3])
        : "r"(a[0]), "r"(a[1]), "r"(a[2]), "r"(a[3]), "r"(b0), "r"(b1));
}
__device__ __forceinline__ uint32_t pack_bf16x2(float lo, float hi) {
    __nv_bfloat162 h = __floats2bfloat162_rn(lo, hi);
    return *reinterpret_cast<uint32_t*>(&h);
}
__device__ __forceinline__ void cp_async16(uint32_t dst, const void* src) {
    asm volatile("cp.async.cg.shared.global [%0], [%1], 16;" :: "r"(dst), "l"(src));
}
#define CP_COMMIT() asm volatile("cp.async.commit_group;" ::: "memory")
#define CP_WAIT1()  asm volatile("cp.async.wait_group 1;" ::: "memory")
#define CP_WAIT0()  asm volatile("cp.async.wait_group 0;" ::: "memory")

// ============ fused converter: weights + x (hi/lo) + bias combine + rope tables ============
#define CVT_BLKS 11584
#define CVT_TOTAL (CVT_BLKS + 3 + 256)

__global__ __launch_bounds__(256)
void cvt_all(const float* __restrict__ wqa, const float* __restrict__ wkva,
             const float* __restrict__ wqb, const float* __restrict__ wkvb,
             const float* __restrict__ wo,  const float* __restrict__ x,
             const float* __restrict__ bq,  const float* __restrict__ bkv)
{
    int blk = blockIdx.x;
    if (blk >= CVT_BLKS) {
        int ex = blk - CVT_BLKS;
        if (ex < 3) {
            int i = ex * 256 + threadIdx.x;
            if (i < QKVW) g_bqkv[i] = (i < QLORA) ? bq[i] : bkv[i - QLORA];
        } else {
            int i = (ex - 3) * 256 + threadIdx.x;   // 0..65535
            int pos = i >> 5, d = i & 31;
            float ang = (float)pos * powf(10000.f, -(float)d * (1.f/32.f));
            float sn, c;
            sincosf(ang, &sn, &c);
            g_ropec[i] = c;
            g_ropes[i] = sn;
        }
        return;
    }
    const float* src;
    __nv_bfloat16 *hi, *lo;
    int base;
    if (blk < 1536)      { src = wqa;  hi = g_wqkvh; lo = g_wqkvl; base = blk; }
    else if (blk < 2112) { src = wkva; hi = g_wqkvh + (size_t)QLORA*DIMX;
                           lo = g_wqkvl + (size_t)QLORA*DIMX; base = blk - 1536; }
    else if (blk < 4416) { src = wqb;  hi = g_wqbh;  lo = g_wqbl;  base = blk - 2112; }
    else if (blk < 5440) { src = wkvb; hi = g_wkvbh; lo = g_wkvbl; base = blk - 4416; }
    else if (blk < 7488) { src = wo;   hi = g_woh;   lo = g_wol;   base = blk - 5440; }
    else                 { src = x;    hi = g_xh;    lo = g_xl;    base = blk - 7488; }

    size_t i0 = (size_t)base * 2048 + threadIdx.x * 4;
#pragma unroll
    for (int rep = 0; rep < 2; rep++) {
        size_t i = i0 + rep * 1024;
        float4 v = *reinterpret_cast<const float4*>(src + i);
        __nv_bfloat162 h01 = __floats2bfloat162_rn(v.x, v.y);
        __nv_bfloat162 h23 = __floats2bfloat162_rn(v.z, v.w);
        __nv_bfloat162 l01 = __floats2bfloat162_rn(v.x - __bfloat162float(h01.x),
                                                   v.y - __bfloat162float(h01.y));
        __nv_bfloat162 l23 = __floats2bfloat162_rn(v.z - __bfloat162float(h23.x),
                                                   v.w - __bfloat162float(h23.y));
        *reinterpret_cast<uint2*>(hi + i) =
            make_uint2(*reinterpret_cast<uint32_t*>(&h01), *reinterpret_cast<uint32_t*>(&h23));
        *reinterpret_cast<uint2*>(lo + i) =
            make_uint2(*reinterpret_cast<uint32_t*>(&l01), *reinterpret_cast<uint32_t*>(&l23));
    }
}

// ============ cp.async 3-stage split-bf16 HMMA GEMM, CTA 128x128, K-tile 32 ============
#define GB_STAGE 32768
#define GB_SMEM  (3*GB_STAGE + 128)

#define GB_MAINLOOP(ACCDECL)                                                    \
    extern __shared__ char smraw[];                                             \
    uint32_t sb0 = smem_to_u32(smraw);                                          \
    uint32_t sb = (sb0 + 127u) & ~127u;                                         \
    const int tid  = threadIdx.x;                                               \
    const int lane = tid & 31;                                                  \
    const int wid  = tid >> 5;                                                  \
    const int bm = blockIdx.y * 128;                                            \
    const int bn = blockIdx.x * 128;                                            \
    const int wm = (wid & 3) * 32;                                              \
    const int wn = (wid >> 2) * 64;                                             \
    const int nk = K >> 5;                                                      \
    ACCDECL                                                                     \
    GB_ISSUE(0); CP_COMMIT();                                                   \
    if (nk > 1) { GB_ISSUE(1); }                                                \
    CP_COMMIT();                                                                \
    for (int kt = 0; kt < nk; kt++) {                                           \
        CP_WAIT1();                                                             \
        __syncthreads();                                                        \
        const uint32_t baseA = sb + (uint32_t)(kt % 3) * GB_STAGE;              \
        const uint32_t baseB = baseA + 16384u;                                  \
        _Pragma("unroll")                                                       \
        for (int k16 = 0; k16 < 2; k16++) {                                     \
            uint32_t ah[2][4], al[2][4];                                        \
            _Pragma("unroll")                                                   \
            for (int mt = 0; mt < 2; mt++) {                                    \
                uint32_t row = wm + mt*16 + (lane & 15);                        \
                uint32_t off = SWZ64(row*64u + (uint32_t)(k16*32) + ((lane >> 4) << 4)); \
                ldmatrix_x4(ah[mt], baseA + off);                               \
                ldmatrix_x4(al[mt], baseA + 8192u + off);                       \
            }                                                                   \
            _Pragma("unroll")                                                   \
            for (int ng = 0; ng < 4; ng++) {                                    \
                uint32_t bh[4], bl[4];                                          \
                uint32_t nrow = wn + ng*16 + ((lane >> 4) << 3) + (lane & 7);   \
                uint32_t off = SWZ64(nrow*64u + (uint32_t)(k16*32) + (((lane >> 3) & 1) << 4)); \
                ldmatrix_x4(bh, baseB + off);                                   \
                ldmatrix_x4(bl, baseB + 8192u + off);                           \
                _Pragma("unroll")                                               \
                for (int mt = 0; mt < 2; mt++) {                                \
                    float* a0 = acc[mt][2*ng];                                  \
                    float* a1 = acc[mt][2*ng+1];                                \
                    mma_bf16(a0, ah[mt], bh[0], bh[1]);                         \
                    mma_bf16(a0, ah[mt], bl[0], bl[1]);                         \
                    mma_bf16(a0, al[mt], bh[0], bh[1]);                         \
                    mma_bf16(a1, ah[mt], bh[2], bh[3]);                         \
                    mma_bf16(a1, ah[mt], bl[2], bl[3]);                         \
                    mma_bf16(a1, al[mt], bh[2], bh[3]);                         \
                }                                                               \
            }                                                                   \
        }                                                                       \
        __syncthreads();                                                        \
        if (kt + 2 < nk) { GB_ISSUE(kt + 2); }                                  \
        CP_COMMIT();                                                            \
    }

#define GB_ACCDECL \
    float acc[2][8][4]; \
    _Pragma("unroll") \
    for (int mt = 0; mt < 2; mt++) \
        _Pragma("unroll") \
        for (int nt = 0; nt < 8; nt++) \
            _Pragma("unroll") \
            for (int q = 0; q < 4; q++) acc[mt][nt][q] = 0.f;

#define GB_ISSUE(kt_) do {                                                      \
        const uint32_t stb = sb + (uint32_t)((kt_) % 3) * GB_STAGE;             \
        const int k0_ = (kt_) << 5;                                             \
        _Pragma("unroll")                                                       \
        for (int i = 0; i < 8; i++) {                                           \
            const int plane = i >> 1;                                           \
            const int idx = ((i & 1) << 8) + tid;                               \
            const int r = idx >> 2;                                             \
            const int c = idx & 3;                                              \
            uint32_t dst = stb + (uint32_t)plane*8192u                          \
                         + SWZ64((uint32_t)(r*64 + c*16));                      \
            const __nv_bfloat16* srcp;                                          \
            if (plane == 0)      srcp = Ah + (size_t)(bm + r)*lda + k0_ + c*8;  \
            else if (plane == 1) srcp = Al + (size_t)(bm + r)*lda + k0_ + c*8;  \
            else {                                                              \
                int rr = bn + r; if (rr >= Nn) rr = Nn - 1;                     \
                srcp = (plane == 2 ? Bh : Bl) + (size_t)rr*ldw + k0_ + c*8;     \
            }                                                                   \
            cp_async16(dst, srcp);                                              \
        }                                                                       \
    } while (0)

__global__ __launch_bounds__(256, 2)
void gemm_bf(const __nv_bfloat16* __restrict__ Ah, const __nv_bfloat16* __restrict__ Al, int lda,
             const __nv_bfloat16* __restrict__ Bh, const __nv_bfloat16* __restrict__ Bl, int ldw,
             const float* __restrict__ bias,
             float* __restrict__ C, int ldc,
             int Nn, int K)
{
    GB_MAINLOOP(GB_ACCDECL)

#pragma unroll
    for (int nt = 0; nt < 8; nt++) {
        int col = bn + wn + nt*8 + (lane & 3)*2;
        if (col >= Nn) continue;
        float bx = bias[col], by = bias[col+1];
#pragma unroll
        for (int mt = 0; mt < 2; mt++) {
            int row = bm + wm + mt*16 + (lane >> 2);
            *reinterpret_cast<float2*>(C + (size_t)row*ldc + col) =
                make_float2(acc[mt][nt][0] + bx, acc[mt][nt][1] + by);
            *reinterpret_cast<float2*>(C + (size_t)(row+8)*ldc + col) =
                make_float2(acc[mt][nt][2] + bx, acc[mt][nt][3] + by);
        }
    }
}

// q_b GEMM: epilogue applies RoPE (table-based) + scale, writes head-major q planes
__global__ __launch_bounds__(256, 2)
void gemm_bf_q(const __nv_bfloat16* __restrict__ Ah, const __nv_bfloat16* __restrict__ Al, int lda,
               const __nv_bfloat16* __restrict__ Bh, const __nv_bfloat16* __restrict__ Bl, int ldw,
               const float* __restrict__ bias,
               __nv_bfloat16* __restrict__ qfh, __nv_bfloat16* __restrict__ qfl,
               int Nn, int K)
{
    GB_MAINLOOP(GB_ACCDECL)

    const bool ispe = ((((bn + wn) >> 6) % 3) == 2);
    if (!ispe) {
#pragma unroll
        for (int nt = 0; nt < 8; nt++) {
            int col = bn + wn + nt*8 + (lane & 3)*2;
            float bx = bias[col], by = bias[col+1];
            int hh = col / 192;
            int d  = col - hh*192;
#pragma unroll
            for (int mt = 0; mt < 2; mt++)
#pragma unroll
                for (int half = 0; half < 2; half++) {
                    int r = bm + wm + mt*16 + (lane >> 2) + half*8;
                    float v0 = (acc[mt][nt][half*2+0] + bx) * QSCALE;
                    float v1 = (acc[mt][nt][half*2+1] + by) * QSCALE;
                    uint32_t hpk = pack_bf16x2(v0, v1);
                    __nv_bfloat162 hv = *reinterpret_cast<__nv_bfloat162*>(&hpk);
                    uint32_t lpk = pack_bf16x2(v0 - __bfloat162float(hv.x),
                                               v1 - __bfloat162float(hv.y));
                    size_t idx = ((size_t)r*NHEADS + hh)*QKHD + d;
                    *reinterpret_cast<uint32_t*>(qfh + idx) = hpk;
                    *reinterpret_cast<uint32_t*>(qfl + idx) = lpk;
                }
        }
    } else {
#pragma unroll
        for (int nt = 0; nt < 4; nt++) {
            int colA = bn + wn + nt*8 + (lane & 3)*2;
            int hh = colA / 192;
            int dA = colA - hh*192;                  // in [128,160)
            int dd0 = dA - 128;
            float bxA = bias[colA],    byA = bias[colA+1];
            float bxB = bias[colA+32], byB = bias[colA+33];
#pragma unroll
            for (int mt = 0; mt < 2; mt++)
#pragma unroll
                for (int half = 0; half < 2; half++) {
                    int r = bm + wm + mt*16 + (lane >> 2) + half*8;
                    int tb = (r & (SEQL-1))*32 + dd0;
                    float c0 = g_ropec[tb],   s0 = g_ropes[tb];
                    float c1 = g_ropec[tb+1], s1 = g_ropes[tb+1];
                    float x10 = acc[mt][nt][half*2+0]   + bxA;
                    float x11 = acc[mt][nt][half*2+1]   + byA;
                    float x20 = acc[mt][nt+4][half*2+0] + bxB;
                    float x21 = acc[mt][nt+4][half*2+1] + byB;
                    float rA0 = (x10*c0 - x20*s0) * QSCALE;
                    float rA1 = (x11*c1 - x21*s1) * QSCALE;
                    float rB0 = (x20*c0 + x10*s0) * QSCALE;
                    float rB1 = (x21*c1 + x11*s1) * QSCALE;
                    size_t idx = ((size_t)r*NHEADS + hh)*QKHD + dA;
                    uint32_t hA = pack_bf16x2(rA0, rA1);
                    __nv_bfloat162 hva = *reinterpret_cast<__nv_bfloat162*>(&hA);
                    uint32_t lA = pack_bf16x2(rA0 - __bfloat162float(hva.x),
                                              rA1 - __bfloat162float(hva.y));
                    uint32_t hB = pack_bf16x2(rB0, rB1);
                    __nv_bfloat162 hvb = *reinterpret_cast<__nv_bfloat162*>(&hB);
                    uint32_t lB = pack_bf16x2(rB0 - __bfloat162float(hvb.x),
                                              rB1 - __bfloat162float(hvb.y));
                    *reinterpret_cast<uint32_t*>(qfh + idx)      = hA;
                    *reinterpret_cast<uint32_t*>(qfl + idx)      = lA;
                    *reinterpret_cast<uint32_t*>(qfh + idx + 32) = hB;
                    *reinterpret_cast<uint32_t*>(qfl + idx + 32) = lB;
                }
        }
    }
}

// kvb GEMM: epilogue converts directly into head-major bf16 hi/lo K-nope / V planes
__global__ __launch_bounds__(256, 2)
void gemm_bf_kv(const __nv_bfloat16* __restrict__ Ah, const __nv_bfloat16* __restrict__ Al, int lda,
                const __nv_bfloat16* __restrict__ Bh, const __nv_bfloat16* __restrict__ Bl, int ldw,
                const float* __restrict__ bias,
                __nv_bfloat16* __restrict__ kfh, __nv_bfloat16* __restrict__ kfl,
                __nv_bfloat16* __restrict__ vfh, __nv_bfloat16* __restrict__ vfl,
                int Nn, int K)
{
    GB_MAINLOOP(GB_ACCDECL)

#pragma unroll
    for (int nt = 0; nt < 8; nt++) {
        int col = bn + wn + nt*8 + (lane & 3)*2;
        float bx = bias[col], by = bias[col+1];
        int hh = col >> 8;
        int d  = col & 255;
#pragma unroll
        for (int mt = 0; mt < 2; mt++) {
            int row = bm + wm + mt*16 + (lane >> 2);
#pragma unroll
            for (int half = 0; half < 2; half++) {
                float v0 = acc[mt][nt][half*2+0] + bx;
                float v1 = acc[mt][nt][half*2+1] + by;
                int r = row + half*8;
                uint32_t hpk = pack_bf16x2(v0, v1);
                __nv_bfloat162 hv = *reinterpret_cast<__nv_bfloat162*>(&hpk);
                uint32_t lpk = pack_bf16x2(v0 - __bfloat162float(hv.x),
                                           v1 - __bfloat162float(hv.y));
                if (d < 128) {
                    size_t idx = ((size_t)r*NHEADS + hh)*QKHD + d;
                    *reinterpret_cast<uint32_t*>(kfh + idx) = hpk;
                    *reinterpret_cast<uint32_t*>(kfl + idx) = lpk;
                } else {
                    size_t idx = ((size_t)r*NHEADS + hh)*VHD + (d - 128);
                    *reinterpret_cast<uint32_t*>(vfh + idx) = hpk;
                    *reinterpret_cast<uint32_t*>(vfl + idx) = lpk;
                }
            }
        }
    }
}

// ---------------- merged RMSNorm (q, kv_c) + k_pe rope in one launch ----------------
__global__ __launch_bounds__(256)
void rmsnorm_both(const float* __restrict__ qkv,
                  __nv_bfloat16* __restrict__ qh, __nv_bfloat16* __restrict__ ql,
                  __nv_bfloat16* __restrict__ kh, __nv_bfloat16* __restrict__ kl,
                  const float* __restrict__ qw, const float* __restrict__ kw,
                  __nv_bfloat16* __restrict__ kfh, __nv_bfloat16* __restrict__ kfl)
{
    int row = blockIdx.x;
    int which = blockIdx.y;
    if (which == 2) {                        // k_pe rope -> K-rope planes
        int d = threadIdx.x;
        if (d < 32) {
            int s = row & (SEQL - 1);
            float c = g_ropec[s*32 + d], sn = g_ropes[s*32 + d];
            const float* base = qkv + (size_t)row*QKVW + 2048;
            float x1 = base[d], x2 = base[d+32];
            float r1 = x1*c - x2*sn;
            float r2 = x2*c + x1*sn;
            __nv_bfloat16 h1 = __float2bfloat16_rn(r1);
            __nv_bfloat16 l1 = __float2bfloat16_rn(r1 - __bfloat162float(h1));
            __nv_bfloat16 h2 = __float2bfloat16_rn(r2);
            __nv_bfloat16 l2 = __float2bfloat16_rn(r2 - __bfloat162float(h2));
#pragma unroll
            for (int hh = 0; hh < NHEADS; hh++) {
                size_t idx = ((size_t)row*NHEADS + hh)*QKHD + 128 + d;
                kfh[idx]      = h1;
                kfl[idx]      = l1;
                kfh[idx + 32] = h2;
                kfl[idx + 32] = l2;
            }
        }
        return;
    }
    int width = which ? KVLORA : QLORA;
    const float* s = qkv + (size_t)row * QKVW + (which ? QLORA : 0);
    const float* w = which ? kw : qw;
    __nv_bfloat16* dh = which ? (kh + (size_t)row*KVLORA) : (qh + (size_t)row*QLORA);
    __nv_bfloat16* dl = which ? (kl + (size_t)row*KVLORA) : (ql + (size_t)row*QLORA);

    float ss = 0.f;
    for (int c = threadIdx.x; c < width; c += blockDim.x) { float v = s[c]; ss += v*v; }

    __shared__ float red[8];
#pragma unroll
    for (int off = 16; off; off >>= 1) ss += __shfl_xor_sync(0xffffffffu, ss, off);
    int warp = threadIdx.x >> 5;
    if ((threadIdx.x & 31) == 0) red[warp] = ss;
    __syncthreads();
    if (warp == 0) {
        float v = (threadIdx.x < 8) ? red[threadIdx.x] : 0.f;
#pragma unroll
        for (int off = 4; off; off >>= 1) v += __shfl_xor_sync(0xffffffffu, v, off);
        if (threadIdx.x == 0) red[0] = v;
    }
    __syncthreads();
    float scale = rsqrtf(red[0] / (float)width + 1e-6f);
    for (int c = threadIdx.x; c < width; c += blockDim.x) {
        float v = s[c] * scale * w[c];
        __nv_bfloat16 hv = __float2bfloat16_rn(v);
        dh[c] = hv;
        dl[c] = __float2bfloat16_rn(v - __bfloat162float(hv));
    }
}

// ============ Flash attention: cp.async Q/K/V planes, split wait groups ============
#define FL_QH 0
#define FL_QL 49152
#define FL_KH 98304
#define FL_KL 122880
#define FL_VH 147456
#define FL_VL 163840
#define FL_SMEM 180224

__global__ __launch_bounds__(256, 1)
void flash_mma(const __nv_bfloat16* __restrict__ qfh, const __nv_bfloat16* __restrict__ qfl,
               const __nv_bfloat16* __restrict__ kfh, const __nv_bfloat16* __restrict__ kfl,
               const __nv_bfloat16* __restrict__ vfh, const __nv_bfloat16* __restrict__ vfl,
               __nv_bfloat16* __restrict__ atth,
               __nv_bfloat16* __restrict__ attl)
{
    extern __shared__ char smraw[];
    uint32_t sb0 = smem_to_u32(smraw);
    uint32_t sb = (sb0 + 127u) & ~127u;

    const int qt = (int)gridDim.x - 1 - (int)blockIdx.x;
    const int h  = blockIdx.y;
    const int b  = blockIdx.z;
    const int s0 = qt * 128;
    const int bb = b * SEQL;
    const int tid  = threadIdx.x;
    const int lane = tid & 31;
    const int wid  = tid >> 5;
    const int wrow = wid * 16;

#pragma unroll
    for (int i = 0; i < 24; i++) {
        int idx = tid + i*256;
        int cidx = idx;
        const __nv_bfloat16* src;
        uint32_t base;
        if (cidx < 3072) { src = qfh; base = (uint32_t)FL_QH; }
        else             { src = qfl; base = (uint32_t)FL_QL; cidx -= 3072; }
        int row = cidx / 24;
        int c = cidx - row*24;
        int ch = c >> 3;
        int dc8 = (c & 7) * 8;
        uint32_t dst = sb + base + ch*16384u + SWZ((uint32_t)(row*128 + dc8*2));
        cp_async16(dst, src + ((size_t)(bb + s0 + row)*NHEADS + h)*QKHD + ch*64 + dc8);
    }
    CP_COMMIT();

    float oc[16][4];
#pragma unroll
    for (int nt = 0; nt < 16; nt++)
#pragma unroll
        for (int q = 0; q < 4; q++) oc[nt][q] = 0.f;
    float m0 = -1e30f, m1 = -1e30f, l0 = 0.f, l1 = 0.f;

    const int rg0 = s0 + wrow + (lane >> 2);
    const int rg1 = rg0 + 8;
    const int nkt = 2*qt + 2;

    for (int kt = 0; kt < nkt; kt++) {
        if (kt > 0) __syncthreads();
        const int ks0 = kt * 64;

#pragma unroll
        for (int i = 0; i < 12; i++) {
            int idx = tid + i*256;
            int cidx = idx;
            const __nv_bfloat16* src;
            uint32_t base;
            if (cidx < 1536) { src = kfh; base = (uint32_t)FL_KH; }
            else             { src = kfl; base = (uint32_t)FL_KL; cidx -= 1536; }
            int row = cidx / 24;
            int c = cidx - row*24;
            int ch = c >> 3;
            int dc8 = (c & 7) * 8;
            uint32_t dst = sb + base + ch*8192u + SWZ((uint32_t)(row*128 + dc8*2));
            cp_async16(dst, src + ((size_t)(bb + ks0 + row)*NHEADS + h)*QKHD + ch*64 + dc8);
        }
        CP_COMMIT();
#pragma unroll
        for (int i = 0; i < 8; i++) {
            int idx = tid + i*256;
            int cidx = idx;
            const __nv_bfloat16* src;
            uint32_t base;
            if (cidx < 1024) { src = vfh; base = (uint32_t)FL_VH; }
            else             { src = vfl; base = (uint32_t)FL_VL; cidx -= 1024; }
            int row = cidx >> 4;
            int c = cidx & 15;
            int ch = c >> 3;
            int dc8 = (c & 7) * 8;
            uint32_t dst = sb + base + ch*8192u + SWZ((uint32_t)(row*128 + dc8*2));
            cp_async16(dst, src + ((size_t)(bb + ks0 + row)*NHEADS + h)*VHD + ch*64 + dc8);
        }
        CP_COMMIT();

        CP_WAIT1();
        __syncthreads();

        const bool active = (ks0 <= s0 + wrow + 15);
        float sc[8][4];
        if (active) {
#pragma unroll
            for (int nt = 0; nt < 8; nt++)
#pragma unroll
                for (int q = 0; q < 4; q++) sc[nt][q] = 0.f;

#pragma unroll
            for (int ks = 0; ks < 12; ks++) {
                int ch = ks >> 2;
                uint32_t kb = (uint32_t)((ks & 3) * 32);
                uint32_t ah[4], al[4];
                {
                    uint32_t row = wrow + (lane & 15);
                    uint32_t off = SWZ(row*128u + kb + ((lane >> 4) << 4));
                    ldmatrix_x4(ah, sb + FL_QH + ch*16384 + off);
                    ldmatrix_x4(al, sb + FL_QL + ch*16384 + off);
                }
                uint32_t bh[16], bl[16];
#pragma unroll
                for (int ng = 0; ng < 4; ng++) {
                    uint32_t nrow = ng*16 + ((lane >> 4) << 3) + (lane & 7);
                    uint32_t off = SWZ(nrow*128u + kb + (((lane >> 3) & 1) << 4));
                    ldmatrix_x4(&bh[ng*4], sb + FL_KH + ch*8192 + off);
                    ldmatrix_x4(&bl[ng*4], sb + FL_KL + ch*8192 + off);
                }
#pragma unroll
                for (int nt = 0; nt < 8; nt++) {
                    mma_bf16(sc[nt], ah, bh[nt*2], bh[nt*2+1]);
                    mma_bf16(sc[nt], ah, bl[nt*2], bl[nt*2+1]);
                    mma_bf16(sc[nt], al, bh[nt*2], bh[nt*2+1]);
                }
            }

            if (ks0 + 63 > s0 + wrow) {
#pragma unroll
                for (int nt = 0; nt < 8; nt++) {
                    int colg = ks0 + nt*8 + (lane & 3)*2;
                    if (colg     > rg0) sc[nt][0] = -1e30f;
                    if (colg + 1 > rg0) sc[nt][1] = -1e30f;
                    if (colg     > rg1) sc[nt][2] = -1e30f;
                    if (colg + 1 > rg1) sc[nt][3] = -1e30f;
                }
            }

            float mx0 = -1e30f, mx1 = -1e30f;
#pragma unroll
            for (int nt = 0; nt < 8; nt++) {
                mx0 = fmaxf(mx0, fmaxf(sc[nt][0], sc[nt][1]));
                mx1 = fmaxf(mx1, fmaxf(sc[nt][2], sc[nt][3]));
            }
            mx0 = fmaxf(mx0, __shfl_xor_sync(0xffffffffu, mx0, 1));
            mx0 = fmaxf(mx0, __shfl_xor_sync(0xffffffffu, mx0, 2));
            mx1 = fmaxf(mx1, __shfl_xor_sync(0xffffffffu, mx1, 1));
            mx1 = fmaxf(mx1, __shfl_xor_sync(0xffffffffu, mx1, 2));
            float mn0 = fmaxf(m0, mx0), mn1 = fmaxf(m1, mx1);
            float a0 = __expf(m0 - mn0), a1 = __expf(m1 - mn1);
            m0 = mn0; m1 = mn1;
            float rs0 = 0.f, rs1 = 0.f;
#pragma unroll
            for (int nt = 0; nt < 8; nt++) {
                sc[nt][0] = __expf(sc[nt][0] - mn0); rs0 += sc[nt][0];
                sc[nt][1] = __expf(sc[nt][1] - mn0); rs0 += sc[nt][1];
                sc[nt][2] = __expf(sc[nt][2] - mn1); rs1 += sc[nt][2];
                sc[nt][3] = __expf(sc[nt][3] - mn1); rs1 += sc[nt][3];
            }
            rs0 += __shfl_xor_sync(0xffffffffu, rs0, 1);
            rs0 += __shfl_xor_sync(0xffffffffu, rs0, 2);
            rs1 += __shfl_xor_sync(0xffffffffu, rs1, 1);
            rs1 += __shfl_xor_sync(0xffffffffu, rs1, 2);
            l0 = l0*a0 + rs0;
            l1 = l1*a1 + rs1;
#pragma unroll
            for (int nt = 0; nt < 16; nt++) {
                oc[nt][0] *= a0; oc[nt][1] *= a0;
                oc[nt][2] *= a1; oc[nt][3] *= a1;
            }
        }

        CP_WAIT0();
        __syncthreads();

        if (active) {
#pragma unroll
            for (int kp = 0; kp < 4; kp++) {
                uint32_t ph[4], pl[4];
                {
                    float p0 = sc[2*kp][0],  p1 = sc[2*kp][1];
                    float p2 = sc[2*kp][2],  p3 = sc[2*kp][3];
                    float p4 = sc[2*kp+1][0], p5 = sc[2*kp+1][1];
                    float p6 = sc[2*kp+1][2], p7 = sc[2*kp+1][3];
                    ph[0] = pack_bf16x2(p0, p1);
                    ph[1] = pack_bf16x2(p2, p3);
                    ph[2] = pack_bf16x2(p4, p5);
                    ph[3] = pack_bf16x2(p6, p7);
                    __nv_bfloat162* hp;
                    hp = reinterpret_cast<__nv_bfloat162*>(&ph[0]);
                    pl[0] = pack_bf16x2(p0 - __bfloat162float(hp->x), p1 - __bfloat162float(hp->y));
                    hp = reinterpret_cast<__nv_bfloat162*>(&ph[1]);
                    pl[1] = pack_bf16x2(p2 - __bfloat162float(hp->x), p3 - __bfloat162float(hp->y));
                    hp = reinterpret_cast<__nv_bfloat162*>(&ph[2]);
                    pl[2] = pack_bf16x2(p4 - __bfloat162float(hp->x), p5 - __bfloat162float(hp->y));
                    hp = reinterpret_cast<__nv_bfloat162*>(&ph[3]);
                    pl[3] = pack_bf16x2(p6 - __bfloat162float(hp->x), p7 - __bfloat162float(hp->y));
                }
#pragma unroll
                for (int ng = 0; ng < 8; ng++) {
                    int ch = ng >> 2;
                    uint32_t n0 = (uint32_t)((ng & 3)*16) + ((lane >> 4) << 3);
                    uint32_t krow = (uint32_t)(kp*16) + (lane & 15);
                    uint32_t off = SWZ(krow*128u + n0*2u);
                    uint32_t vh[4], vl[4];
                    ldmatrix_x4_trans(vh, sb + FL_VH + ch*8192 + off);
                    ldmatrix_x4_trans(vl, sb + FL_VL + ch*8192 + off);
                    mma_bf16(oc[ng*2],   ph, vh[0], vh[1]);
                    mma_bf16(oc[ng*2],   ph, vl[0], vl[1]);
                    mma_bf16(oc[ng*2],   pl, vh[0], vh[1]);
                    mma_bf16(oc[ng*2+1], ph, vh[2], vh[3]);
                    mma_bf16(oc[ng*2+1], ph, vl[2], vl[3]);
                    mma_bf16(oc[ng*2+1], pl, vh[2], vh[3]);
                }
            }
        }
    }

    float inv0 = 1.f / l0, inv1 = 1.f / l1;
    int row0 = bb + s0 + wrow + (lane >> 2);
    int row1 = row0 + 8;
#pragma unroll
    for (int nt = 0; nt < 16; nt++) {
        int col = h*128 + nt*8 + (lane & 3)*2;
        float o0 = oc[nt][0]*inv0, o1 = oc[nt][1]*inv0;
        float o2 = oc[nt][2]*inv1, o3 = oc[nt][3]*inv1;
        uint32_t h0 = pack_bf16x2(o0, o1);
        __nv_bfloat162 hv0 = *reinterpret_cast<__nv_bfloat162*>(&h0);
        uint32_t l0p = pack_bf16x2(o0 - __bfloat162float(hv0.x), o1 - __bfloat162float(hv0.y));
        uint32_t h1 = pack_bf16x2(o2, o3);
        __nv_bfloat162 hv1 = *reinterpret_cast<__nv_bfloat162*>(&h1);
        uint32_t l1p = pack_bf16x2(o2 - __bfloat162float(hv1.x), o3 - __bfloat162float(hv1.y));
        *reinterpret_cast<uint32_t*>(atth + (size_t)row0*2048 + col) = h0;
        *reinterpret_cast<uint32_t*>(attl + (size_t)row0*2048 + col) = l0p;
        *reinterpret_cast<uint32_t*>(atth + (size_t)row1*2048 + col) = h1;
        *reinterpret_cast<uint32_t*>(attl + (size_t)row1*2048 + col) = l1p;
    }
}

// ---------------- host launcher ----------------
extern "C" void kernel_launch(void* const* d_in, const int* in_sizes, int n_in,
                              void* d_out, int out_size)
{
    const float* x      = (const float*)d_in[0];
    const float* wqa    = (const float*)d_in[1];
    const float* wqa_b  = (const float*)d_in[2];
    const float* qnw    = (const float*)d_in[3];
    const float* wqb    = (const float*)d_in[4];
    const float* wqb_b  = (const float*)d_in[5];
    const float* wkva   = (const float*)d_in[6];
    const float* wkva_b = (const float*)d_in[7];
    const float* kvnw   = (const float*)d_in[8];
    const float* wkvb   = (const float*)d_in[9];
    const float* wkvb_b = (const float*)d_in[10];
    const float* wo     = (const float*)d_in[11];
    const float* wo_b   = (const float*)d_in[12];
    float* out = (float*)d_out;

    float *qkv, *bqkv;
    cudaGetSymbolAddress((void**)&qkv, g_qkv);
    cudaGetSymbolAddress((void**)&bqkv, g_bqkv);
    __nv_bfloat16 *xh,*xl,*qah,*qal,*kvch,*kvcl,*atth,*attl;
    __nv_bfloat16 *wqkvh,*wqkvl,*wqbh,*wqbl,*wkvbh,*wkvbl,*woh,*wol;
    __nv_bfloat16 *kfh,*kfl,*vfh,*vfl,*qfh,*qfl;
    cudaGetSymbolAddress((void**)&xh, g_xh);   cudaGetSymbolAddress((void**)&xl, g_xl);
    cudaGetSymbolAddress((void**)&qah, g_qah); cudaGetSymbolAddress((void**)&qal, g_qal);
    cudaGetSymbolAddress((void**)&kvch, g_kvch); cudaGetSymbolAddress((void**)&kvcl, g_kvcl);
    cudaGetSymbolAddress((void**)&atth, g_atth); cudaGetSymbolAddress((void**)&attl, g_attl);
    cudaGetSymbolAddress((void**)&wqkvh, g_wqkvh); cudaGetSymbolAddress((void**)&wqkvl, g_wqkvl);
    cudaGetSymbolAddress((void**)&wqbh, g_wqbh); cudaGetSymbolAddress((void**)&wqbl, g_wqbl);
    cudaGetSymbolAddress((void**)&wkvbh, g_wkvbh); cudaGetSymbolAddress((void**)&wkvbl, g_wkvbl);
    cudaGetSymbolAddress((void**)&woh, g_woh); cudaGetSymbolAddress((void**)&wol, g_wol);
    cudaGetSymbolAddress((void**)&kfh, g_kfh); cudaGetSymbolAddress((void**)&kfl, g_kfl);
    cudaGetSymbolAddress((void**)&vfh, g_vfh); cudaGetSymbolAddress((void**)&vfl, g_vfl);
    cudaGetSymbolAddress((void**)&qfh, g_qfh); cudaGetSymbolAddress((void**)&qfl, g_qfl);

    cudaFuncSetAttribute(flash_mma, cudaFuncAttributeMaxDynamicSharedMemorySize, FL_SMEM + 128);
    cudaFuncSetAttribute(gemm_bf, cudaFuncAttributeMaxDynamicSharedMemorySize, GB_SMEM);
    cudaFuncSetAttribute(gemm_bf_q, cudaFuncAttributeMaxDynamicSharedMemorySize, GB_SMEM);
    cudaFuncSetAttribute(gemm_bf_kv, cudaFuncAttributeMaxDynamicSharedMemorySize, GB_SMEM);

    dim3 t256(256);

    // 1. fused conversions (weights + x + bias combine + rope tables)
    cvt_all<<<CVT_TOTAL, t256>>>(wqa, wkva, wqb, wkvb, wo, x, wqa_b, wkva_b);
    // 2. merged qkv = x @ [wq_a; wkv_a]^T + b
    gemm_bf<<<dim3((QKVW+127)/128, ROWS/128), t256, GB_SMEM>>>(xh, xl, DIMX, wqkvh, wqkvl, DIMX, bqkv, qkv, QKVW, QKVW, DIMX);
    // 3. rmsnorm q + kv_c + k_pe rope (one launch)
    rmsnorm_both<<<dim3(ROWS, 3), t256>>>(qkv, qah, qal, kvch, kvcl, qnw, kvnw, kfh, kfl);
    // 4. q_b GEMM with fused RoPE(table) + scale + bf16 plane epilogue
    gemm_bf_q<<<dim3(3072/128, ROWS/128), t256, GB_SMEM>>>(qah, qal, QLORA, wqbh, wqbl, QLORA, wqb_b, qfh, qfl, 3072, QLORA);
    // 5. kvb GEMM with fused bf16 plane epilogue
    gemm_bf_kv<<<dim3(4096/128, ROWS/128), t256, GB_SMEM>>>(kvch, kvcl, KVLORA, wkvbh, wkvbl, KVLORA, wkvb_b, kfh, kfl, vfh, vfl, 4096, KVLORA);
    // 6. flash (all operands via cp.async bf16 planes)
    flash_mma<<<dim3(SEQL/128, NHEADS, BSZ), t256, FL_SMEM + 128>>>(qfh, qfl, kfh, kfl, vfh, vfl, atth, attl);
    // 7. out
    gemm_bf<<<dim3(2048/128, ROWS/128), t256, GB_SMEM>>>(atth, attl, 2048, woh, wol, 2048, wo_b, out, 2048, 2048, DIMX);
}

// round 16
// speedup vs baseline: 1.0047x; 1.0047x over previous
#include <cuda_runtime.h>
#include <cuda_bf16.h>
#include <cstdint>
#include <math.h>

#define SEQL   2048
#define BSZ    2
#define ROWS   (BSZ*SEQL)          // 4096
#define DIMX   2048
#define QLORA  1536
#define KVLORA 512
#define NHEADS 16
#define QKHD   192
#define NOPE_D 128
#define ROPE_D 64
#define VHD    128
#define QKVW   2112                // 1536 q + 512 kv_c + 64 k_pe
#define QSCALE 0.07216878364870323f

// ---------------- scratch (static device globals; no allocation) ----------------
__device__ float g_qkv[ROWS*QKVW];
__device__ float g_bqkv[QKVW];
__device__ float g_ropec[SEQL*32], g_ropes[SEQL*32];

__device__ __nv_bfloat16 g_xh  [ROWS*DIMX],   g_xl  [ROWS*DIMX];
__device__ __nv_bfloat16 g_qah [ROWS*QLORA],  g_qal [ROWS*QLORA];
__device__ __nv_bfloat16 g_kvch[ROWS*KVLORA], g_kvcl[ROWS*KVLORA];
__device__ __nv_bfloat16 g_atth[ROWS*2048],   g_attl[ROWS*2048];
__device__ __nv_bfloat16 g_wqkvh[QKVW*DIMX],  g_wqkvl[QKVW*DIMX];
__device__ __nv_bfloat16 g_wqbh[3072*QLORA],  g_wqbl[3072*QLORA];
__device__ __nv_bfloat16 g_wkvbh[4096*KVLORA],g_wkvbl[4096*KVLORA];
__device__ __nv_bfloat16 g_woh [DIMX*2048],   g_wol [DIMX*2048];
__device__ __nv_bfloat16 g_kfh[ROWS*NHEADS*QKHD], g_kfl[ROWS*NHEADS*QKHD];
__device__ __nv_bfloat16 g_vfh[ROWS*NHEADS*VHD],  g_vfl[ROWS*NHEADS*VHD];
__device__ __nv_bfloat16 g_qfh[ROWS*NHEADS*QKHD], g_qfl[ROWS*NHEADS*QKHD];

__device__ __forceinline__ uint32_t smem_to_u32(const void* p) {
    uint32_t a;
    asm("{ .reg .u64 t; cvta.to.shared.u64 t, %1; cvt.u32.u64 %0, t; }" : "=r"(a) : "l"(p));
    return a;
}
#define SWZ(x)   ((x) ^ (((x) >> 3) & 0x70))
#define SWZ64(x) ((x) ^ (((x) >> 3) & 0x30))

__device__ __forceinline__ void ldmatrix_x4(uint32_t* r, uint32_t addr) {
    asm volatile("ldmatrix.sync.aligned.m8n8.x4.shared.b16 {%0,%1,%2,%3}, [%4];"
        : "=r"(r[0]), "=r"(r[1]), "=r"(r[2]), "=r"(r[3]) : "r"(addr));
}
__device__ __forceinline__ void ldmatrix_x4_trans(uint32_t* r, uint32_t addr) {
    asm volatile("ldmatrix.sync.aligned.m8n8.x4.trans.shared.b16 {%0,%1,%2,%3}, [%4];"
        : "=r"(r[0]), "=r"(r[1]), "=r"(r[2]), "=r"(r[3]) : "r"(addr));
}
__device__ __forceinline__ void mma_bf16(float* c, const uint32_t* a, uint32_t b0, uint32_t b1) {
    asm volatile(
        "mma.sync.aligned.m16n8k16.row.col.f32.bf16.bf16.f32 "
        "{%0,%1,%2,%3}, {%4,%5,%6,%7}, {%8,%9}, {%0,%1,%2,%3};"
        : "+f"(c[0]), "+f"(c[1]), "+f"(c[2]), "+f"(c[3])
        : "r"(a[0]), "r"(a[1]), "r"(a[2]), "r"(a[3]), "r"(b0), "r"(b1));
}
__device__ __forceinline__ uint32_t pack_bf16x2(float lo, float hi) {
    __nv_bfloat162 h = __floats2bfloat162_rn(lo, hi);
    return *reinterpret_cast<uint32_t*>(&h);
}
__device__ __forceinline__ void cp_async16(uint32_t dst, const void* src) {
    asm volatile("cp.async.cg.shared.global [%0], [%1], 16;" :: "r"(dst), "l"(src));
}
#define CP_COMMIT() asm volatile("cp.async.commit_group;" ::: "memory")
#define CP_WAIT1()  asm volatile("cp.async.wait_group 1;" ::: "memory")
#define CP_WAIT0()  asm volatile("cp.async.wait_group 0;" ::: "memory")

// ============ fused converter: weights + x (hi/lo) + bias combine + rope tables ============
#define CVT_BLKS 11584
#define CVT_TOTAL (CVT_BLKS + 3 + 256)

__global__ __launch_bounds__(256)
void cvt_all(const float* __restrict__ wqa, const float* __restrict__ wkva,
             const float* __restrict__ wqb, const float* __restrict__ wkvb,
             const float* __restrict__ wo,  const float* __restrict__ x,
             const float* __restrict__ bq,  const float* __restrict__ bkv)
{
    int blk = blockIdx.x;
    if (blk >= CVT_BLKS) {
        int ex = blk - CVT_BLKS;
        if (ex < 3) {
            int i = ex * 256 + threadIdx.x;
            if (i < QKVW) g_bqkv[i] = (i < QLORA) ? bq[i] : bkv[i - QLORA];
        } else {
            int i = (ex - 3) * 256 + threadIdx.x;
            int pos = i >> 5, d = i & 31;
            float ang = (float)pos * powf(10000.f, -(float)d * (1.f/32.f));
            float sn, c;
            sincosf(ang, &sn, &c);
            g_ropec[i] = c;
            g_ropes[i] = sn;
        }
        return;
    }
    const float* src;
    __nv_bfloat16 *hi, *lo;
    int base;
    if (blk < 1536)      { src = wqa;  hi = g_wqkvh; lo = g_wqkvl; base = blk; }
    else if (blk < 2112) { src = wkva; hi = g_wqkvh + (size_t)QLORA*DIMX;
                           lo = g_wqkvl + (size_t)QLORA*DIMX; base = blk - 1536; }
    else if (blk < 4416) { src = wqb;  hi = g_wqbh;  lo = g_wqbl;  base = blk - 2112; }
    else if (blk < 5440) { src = wkvb; hi = g_wkvbh; lo = g_wkvbl; base = blk - 4416; }
    else if (blk < 7488) { src = wo;   hi = g_woh;   lo = g_wol;   base = blk - 5440; }
    else                 { src = x;    hi = g_xh;    lo = g_xl;    base = blk - 7488; }

    size_t i0 = (size_t)base * 2048 + threadIdx.x * 4;
#pragma unroll
    for (int rep = 0; rep < 2; rep++) {
        size_t i = i0 + rep * 1024;
        float4 v = *reinterpret_cast<const float4*>(src + i);
        __nv_bfloat162 h01 = __floats2bfloat162_rn(v.x, v.y);
        __nv_bfloat162 h23 = __floats2bfloat162_rn(v.z, v.w);
        __nv_bfloat162 l01 = __floats2bfloat162_rn(v.x - __bfloat162float(h01.x),
                                                   v.y - __bfloat162float(h01.y));
        __nv_bfloat162 l23 = __floats2bfloat162_rn(v.z - __bfloat162float(h23.x),
                                                   v.w - __bfloat162float(h23.y));
        *reinterpret_cast<uint2*>(hi + i) =
            make_uint2(*reinterpret_cast<uint32_t*>(&h01), *reinterpret_cast<uint32_t*>(&h23));
        *reinterpret_cast<uint2*>(lo + i) =
            make_uint2(*reinterpret_cast<uint32_t*>(&l01), *reinterpret_cast<uint32_t*>(&l23));
    }
}

// ============ cp.async 3-stage split-bf16 HMMA GEMM, CTA 128x128, K-tile 32 ============
#define GB_STAGE 32768
#define GB_SMEM  (3*GB_STAGE + 128)

#define GB_MAINLOOP(ACCDECL)                                                    \
    extern __shared__ char smraw[];                                             \
    uint32_t sb0 = smem_to_u32(smraw);                                          \
    uint32_t sb = (sb0 + 127u) & ~127u;                                         \
    const int tid  = threadIdx.x;                                               \
    const int lane = tid & 31;                                                  \
    const int wid  = tid >> 5;                                                  \
    const int bm = blockIdx.y * 128;                                            \
    const int bn = blockIdx.x * 128;                                            \
    const int wm = (wid & 3) * 32;                                              \
    const int wn = (wid >> 2) * 64;                                             \
    const int nk = K >> 5;                                                      \
    ACCDECL                                                                     \
    GB_ISSUE(0); CP_COMMIT();                                                   \
    if (nk > 1) { GB_ISSUE(1); }                                                \
    CP_COMMIT();                                                                \
    for (int kt = 0; kt < nk; kt++) {                                           \
        CP_WAIT1();                                                             \
        __syncthreads();                                                        \
        const uint32_t baseA = sb + (uint32_t)(kt % 3) * GB_STAGE;              \
        const uint32_t baseB = baseA + 16384u;                                  \
        _Pragma("unroll")                                                       \
        for (int k16 = 0; k16 < 2; k16++) {                                     \
            uint32_t ah[2][4], al[2][4];                                        \
            _Pragma("unroll")                                                   \
            for (int mt = 0; mt < 2; mt++) {                                    \
                uint32_t row = wm + mt*16 + (lane & 15);                        \
                uint32_t off = SWZ64(row*64u + (uint32_t)(k16*32) + ((lane >> 4) << 4)); \
                ldmatrix_x4(ah[mt], baseA + off);                               \
                ldmatrix_x4(al[mt], baseA + 8192u + off);                       \
            }                                                                   \
            _Pragma("unroll")                                                   \
            for (int ng = 0; ng < 4; ng++) {                                    \
                uint32_t bh[4], bl[4];                                          \
                uint32_t nrow = wn + ng*16 + ((lane >> 4) << 3) + (lane & 7);   \
                uint32_t off = SWZ64(nrow*64u + (uint32_t)(k16*32) + (((lane >> 3) & 1) << 4)); \
                ldmatrix_x4(bh, baseB + off);                                   \
                ldmatrix_x4(bl, baseB + 8192u + off);                           \
                _Pragma("unroll")                                               \
                for (int mt = 0; mt < 2; mt++) {                                \
                    float* a0 = acc[mt][2*ng];                                  \
                    float* a1 = acc[mt][2*ng+1];                                \
                    mma_bf16(a0, ah[mt], bh[0], bh[1]);                         \
                    mma_bf16(a0, ah[mt], bl[0], bl[1]);                         \
                    mma_bf16(a0, al[mt], bh[0], bh[1]);                         \
                    mma_bf16(a1, ah[mt], bh[2], bh[3]);                         \
                    mma_bf16(a1, ah[mt], bl[2], bl[3]);                         \
                    mma_bf16(a1, al[mt], bh[2], bh[3]);                         \
                }                                                               \
            }                                                                   \
        }                                                                       \
        __syncthreads();                                                        \
        if (kt + 2 < nk) { GB_ISSUE(kt + 2); }                                  \
        CP_COMMIT();                                                            \
    }

#define GB_ACCDECL \
    float acc[2][8][4]; \
    _Pragma("unroll") \
    for (int mt = 0; mt < 2; mt++) \
        _Pragma("unroll") \
        for (int nt = 0; nt < 8; nt++) \
            _Pragma("unroll") \
            for (int q = 0; q < 4; q++) acc[mt][nt][q] = 0.f;

#define GB_ISSUE(kt_) do {                                                      \
        const uint32_t stb = sb + (uint32_t)((kt_) % 3) * GB_STAGE;             \
        const int k0_ = (kt_) << 5;                                             \
        _Pragma("unroll")                                                       \
        for (int i = 0; i < 8; i++) {                                           \
            const int plane = i >> 1;                                           \
            const int idx = ((i & 1) << 8) + tid;                               \
            const int r = idx >> 2;                                             \
            const int c = idx & 3;                                              \
            uint32_t dst = stb + (uint32_t)plane*8192u                          \
                         + SWZ64((uint32_t)(r*64 + c*16));                      \
            const __nv_bfloat16* srcp;                                          \
            if (plane == 0)      srcp = Ah + (size_t)(bm + r)*lda + k0_ + c*8;  \
            else if (plane == 1) srcp = Al + (size_t)(bm + r)*lda + k0_ + c*8;  \
            else {                                                              \
                int rr = bn + r; if (rr >= Nn) rr = Nn - 1;                     \
                srcp = (plane == 2 ? Bh : Bl) + (size_t)rr*ldw + k0_ + c*8;     \
            }                                                                   \
            cp_async16(dst, srcp);                                              \
        }                                                                       \
    } while (0)

__global__ __launch_bounds__(256, 2)
void gemm_bf(const __nv_bfloat16* __restrict__ Ah, const __nv_bfloat16* __restrict__ Al, int lda,
             const __nv_bfloat16* __restrict__ Bh, const __nv_bfloat16* __restrict__ Bl, int ldw,
             const float* __restrict__ bias,
             float* __restrict__ C, int ldc,
             int Nn, int K)
{
    GB_MAINLOOP(GB_ACCDECL)

#pragma unroll
    for (int nt = 0; nt < 8; nt++) {
        int col = bn + wn + nt*8 + (lane & 3)*2;
        if (col >= Nn) continue;
        float bx = bias[col], by = bias[col+1];
#pragma unroll
        for (int mt = 0; mt < 2; mt++) {
            int row = bm + wm + mt*16 + (lane >> 2);
            *reinterpret_cast<float2*>(C + (size_t)row*ldc + col) =
                make_float2(acc[mt][nt][0] + bx, acc[mt][nt][1] + by);
            *reinterpret_cast<float2*>(C + (size_t)(row+8)*ldc + col) =
                make_float2(acc[mt][nt][2] + bx, acc[mt][nt][3] + by);
        }
    }
}

// q_b GEMM: epilogue applies RoPE (table-based) + scale, writes head-major q planes
__global__ __launch_bounds__(256, 2)
void gemm_bf_q(const __nv_bfloat16* __restrict__ Ah, const __nv_bfloat16* __restrict__ Al, int lda,
               const __nv_bfloat16* __restrict__ Bh, const __nv_bfloat16* __restrict__ Bl, int ldw,
               const float* __restrict__ bias,
               __nv_bfloat16* __restrict__ qfh, __nv_bfloat16* __restrict__ qfl,
               int Nn, int K)
{
    GB_MAINLOOP(GB_ACCDECL)

    const bool ispe = ((((bn + wn) >> 6) % 3) == 2);
    if (!ispe) {
#pragma unroll
        for (int nt = 0; nt < 8; nt++) {
            int col = bn + wn + nt*8 + (lane & 3)*2;
            float bx = bias[col], by = bias[col+1];
            int hh = col / 192;
            int d  = col - hh*192;
#pragma unroll
            for (int mt = 0; mt < 2; mt++)
#pragma unroll
                for (int half = 0; half < 2; half++) {
                    int r = bm + wm + mt*16 + (lane >> 2) + half*8;
                    float v0 = (acc[mt][nt][half*2+0] + bx) * QSCALE;
                    float v1 = (acc[mt][nt][half*2+1] + by) * QSCALE;
                    uint32_t hpk = pack_bf16x2(v0, v1);
                    __nv_bfloat162 hv = *reinterpret_cast<__nv_bfloat162*>(&hpk);
                    uint32_t lpk = pack_bf16x2(v0 - __bfloat162float(hv.x),
                                               v1 - __bfloat162float(hv.y));
                    size_t idx = ((size_t)r*NHEADS + hh)*QKHD + d;
                    *reinterpret_cast<uint32_t*>(qfh + idx) = hpk;
                    *reinterpret_cast<uint32_t*>(qfl + idx) = lpk;
                }
        }
    } else {
#pragma unroll
        for (int nt = 0; nt < 4; nt++) {
            int colA = bn + wn + nt*8 + (lane & 3)*2;
            int hh = colA / 192;
            int dA = colA - hh*192;
            int dd0 = dA - 128;
            float bxA = bias[colA],    byA = bias[colA+1];
            float bxB = bias[colA+32], byB = bias[colA+33];
#pragma unroll
            for (int mt = 0; mt < 2; mt++)
#pragma unroll
                for (int half = 0; half < 2; half++) {
                    int r = bm + wm + mt*16 + (lane >> 2) + half*8;
                    int tb = (r & (SEQL-1))*32 + dd0;
                    float c0 = g_ropec[tb],   s0 = g_ropes[tb];
                    float c1 = g_ropec[tb+1], s1 = g_ropes[tb+1];
                    float x10 = acc[mt][nt][half*2+0]   + bxA;
                    float x11 = acc[mt][nt][half*2+1]   + byA;
                    float x20 = acc[mt][nt+4][half*2+0] + bxB;
                    float x21 = acc[mt][nt+4][half*2+1] + byB;
                    float rA0 = (x10*c0 - x20*s0) * QSCALE;
                    float rA1 = (x11*c1 - x21*s1) * QSCALE;
                    float rB0 = (x20*c0 + x10*s0) * QSCALE;
                    float rB1 = (x21*c1 + x11*s1) * QSCALE;
                    size_t idx = ((size_t)r*NHEADS + hh)*QKHD + dA;
                    uint32_t hA = pack_bf16x2(rA0, rA1);
                    __nv_bfloat162 hva = *reinterpret_cast<__nv_bfloat162*>(&hA);
                    uint32_t lA = pack_bf16x2(rA0 - __bfloat162float(hva.x),
                                              rA1 - __bfloat162float(hva.y));
                    uint32_t hB = pack_bf16x2(rB0, rB1);
                    __nv_bfloat162 hvb = *reinterpret_cast<__nv_bfloat162*>(&hB);
                    uint32_t lB = pack_bf16x2(rB0 - __bfloat162float(hvb.x),
                                              rB1 - __bfloat162float(hvb.y));
                    *reinterpret_cast<uint32_t*>(qfh + idx)      = hA;
                    *reinterpret_cast<uint32_t*>(qfl + idx)      = lA;
                    *reinterpret_cast<uint32_t*>(qfh + idx + 32) = hB;
                    *reinterpret_cast<uint32_t*>(qfl + idx + 32) = lB;
                }
        }
    }
}

// kvb GEMM: epilogue converts directly into head-major bf16 hi/lo K-nope / V planes
__global__ __launch_bounds__(256, 2)
void gemm_bf_kv(const __nv_bfloat16* __restrict__ Ah, const __nv_bfloat16* __restrict__ Al, int lda,
                const __nv_bfloat16* __restrict__ Bh, const __nv_bfloat16* __restrict__ Bl, int ldw,
                const float* __restrict__ bias,
                __nv_bfloat16* __restrict__ kfh, __nv_bfloat16* __restrict__ kfl,
                __nv_bfloat16* __restrict__ vfh, __nv_bfloat16* __restrict__ vfl,
                int Nn, int K)
{
    GB_MAINLOOP(GB_ACCDECL)

#pragma unroll
    for (int nt = 0; nt < 8; nt++) {
        int col = bn + wn + nt*8 + (lane & 3)*2;
        float bx = bias[col], by = bias[col+1];
        int hh = col >> 8;
        int d  = col & 255;
#pragma unroll
        for (int mt = 0; mt < 2; mt++) {
            int row = bm + wm + mt*16 + (lane >> 2);
#pragma unroll
            for (int half = 0; half < 2; half++) {
                float v0 = acc[mt][nt][half*2+0] + bx;
                float v1 = acc[mt][nt][half*2+1] + by;
                int r = row + half*8;
                uint32_t hpk = pack_bf16x2(v0, v1);
                __nv_bfloat162 hv = *reinterpret_cast<__nv_bfloat162*>(&hpk);
                uint32_t lpk = pack_bf16x2(v0 - __bfloat162float(hv.x),
                                           v1 - __bfloat162float(hv.y));
                if (d < 128) {
                    size_t idx = ((size_t)r*NHEADS + hh)*QKHD + d;
                    *reinterpret_cast<uint32_t*>(kfh + idx) = hpk;
                    *reinterpret_cast<uint32_t*>(kfl + idx) = lpk;
                } else {
                    size_t idx = ((size_t)r*NHEADS + hh)*VHD + (d - 128);
                    *reinterpret_cast<uint32_t*>(vfh + idx) = hpk;
                    *reinterpret_cast<uint32_t*>(vfl + idx) = lpk;
                }
            }
        }
    }
}

// ---------------- merged RMSNorm (q, kv_c) + k_pe rope in one launch ----------------
__global__ __launch_bounds__(256)
void rmsnorm_both(const float* __restrict__ qkv,
                  __nv_bfloat16* __restrict__ qh, __nv_bfloat16* __restrict__ ql,
                  __nv_bfloat16* __restrict__ kh, __nv_bfloat16* __restrict__ kl,
                  const float* __restrict__ qw, const float* __restrict__ kw,
                  __nv_bfloat16* __restrict__ kfh, __nv_bfloat16* __restrict__ kfl)
{
    int row = blockIdx.x;
    int which = blockIdx.y;
    if (which == 2) {
        int d = threadIdx.x;
        if (d < 32) {
            int s = row & (SEQL - 1);
            float c = g_ropec[s*32 + d], sn = g_ropes[s*32 + d];
            const float* base = qkv + (size_t)row*QKVW + 2048;
            float x1 = base[d], x2 = base[d+32];
            float r1 = x1*c - x2*sn;
            float r2 = x2*c + x1*sn;
            __nv_bfloat16 h1 = __float2bfloat16_rn(r1);
            __nv_bfloat16 l1 = __float2bfloat16_rn(r1 - __bfloat162float(h1));
            __nv_bfloat16 h2 = __float2bfloat16_rn(r2);
            __nv_bfloat16 l2 = __float2bfloat16_rn(r2 - __bfloat162float(h2));
#pragma unroll
            for (int hh = 0; hh < NHEADS; hh++) {
                size_t idx = ((size_t)row*NHEADS + hh)*QKHD + 128 + d;
                kfh[idx]      = h1;
                kfl[idx]      = l1;
                kfh[idx + 32] = h2;
                kfl[idx + 32] = l2;
            }
        }
        return;
    }
    int width = which ? KVLORA : QLORA;
    const float* s = qkv + (size_t)row * QKVW + (which ? QLORA : 0);
    const float* w = which ? kw : qw;
    __nv_bfloat16* dh = which ? (kh + (size_t)row*KVLORA) : (qh + (size_t)row*QLORA);
    __nv_bfloat16* dl = which ? (kl + (size_t)row*KVLORA) : (ql + (size_t)row*QLORA);

    float ss = 0.f;
    for (int c = threadIdx.x; c < width; c += blockDim.x) { float v = s[c]; ss += v*v; }

    __shared__ float red[8];
#pragma unroll
    for (int off = 16; off; off >>= 1) ss += __shfl_xor_sync(0xffffffffu, ss, off);
    int warp = threadIdx.x >> 5;
    if ((threadIdx.x & 31) == 0) red[warp] = ss;
    __syncthreads();
    if (warp == 0) {
        float v = (threadIdx.x < 8) ? red[threadIdx.x] : 0.f;
#pragma unroll
        for (int off = 4; off; off >>= 1) v += __shfl_xor_sync(0xffffffffu, v, off);
        if (threadIdx.x == 0) red[0] = v;
    }
    __syncthreads();
    float scale = rsqrtf(red[0] / (float)width + 1e-6f);
    for (int c = threadIdx.x; c < width; c += blockDim.x) {
        float v = s[c] * scale * w[c];
        __nv_bfloat16 hv = __float2bfloat16_rn(v);
        dh[c] = hv;
        dl[c] = __float2bfloat16_rn(v - __bfloat162float(hv));
    }
}

// ============ Flash attention: single wait-group + 2 barriers per kt ============
#define FL_QH 0
#define FL_QL 49152
#define FL_KH 98304
#define FL_KL 122880
#define FL_VH 147456
#define FL_VL 163840
#define FL_SMEM 180224

__global__ __launch_bounds__(256, 1)
void flash_mma(const __nv_bfloat16* __restrict__ qfh, const __nv_bfloat16* __restrict__ qfl,
               const __nv_bfloat16* __restrict__ kfh, const __nv_bfloat16* __restrict__ kfl,
               const __nv_bfloat16* __restrict__ vfh, const __nv_bfloat16* __restrict__ vfl,
               __nv_bfloat16* __restrict__ atth,
               __nv_bfloat16* __restrict__ attl)
{
    extern __shared__ char smraw[];
    uint32_t sb0 = smem_to_u32(smraw);
    uint32_t sb = (sb0 + 127u) & ~127u;

    const int qt = (int)gridDim.x - 1 - (int)blockIdx.x;
    const int h  = blockIdx.y;
    const int b  = blockIdx.z;
    const int s0 = qt * 128;
    const int bb = b * SEQL;
    const int tid  = threadIdx.x;
    const int lane = tid & 31;
    const int wid  = tid >> 5;
    const int wrow = wid * 16;

    // ---- issue Q loads ----
#pragma unroll
    for (int i = 0; i < 24; i++) {
        int idx = tid + i*256;
        int cidx = idx;
        const __nv_bfloat16* src;
        uint32_t base;
        if (cidx < 3072) { src = qfh; base = (uint32_t)FL_QH; }
        else             { src = qfl; base = (uint32_t)FL_QL; cidx -= 3072; }
        int row = cidx / 24;
        int c = cidx - row*24;
        int ch = c >> 3;
        int dc8 = (c & 7) * 8;
        uint32_t dst = sb + base + ch*16384u + SWZ((uint32_t)(row*128 + dc8*2));
        cp_async16(dst, src + ((size_t)(bb + s0 + row)*NHEADS + h)*QKHD + ch*64 + dc8);
    }
    CP_COMMIT();

    float oc[16][4];
#pragma unroll
    for (int nt = 0; nt < 16; nt++)
#pragma unroll
        for (int q = 0; q < 4; q++) oc[nt][q] = 0.f;
    float m0 = -1e30f, m1 = -1e30f, l0 = 0.f, l1 = 0.f;

    const int rg0 = s0 + wrow + (lane >> 2);
    const int rg1 = rg0 + 8;
    const int nkt = 2*qt + 2;

    for (int kt = 0; kt < nkt; kt++) {
        if (kt > 0) __syncthreads();       // all warps done reading previous K/V smem
        const int ks0 = kt * 64;

        // ---- issue K + V loads (one commit group) ----
#pragma unroll
        for (int i = 0; i < 12; i++) {
            int idx = tid + i*256;
            int cidx = idx;
            const __nv_bfloat16* src;
            uint32_t base;
            if (cidx < 1536) { src = kfh; base = (uint32_t)FL_KH; }
            else             { src = kfl; base = (uint32_t)FL_KL; cidx -= 1536; }
            int row = cidx / 24;
            int c = cidx - row*24;
            int ch = c >> 3;
            int dc8 = (c & 7) * 8;
            uint32_t dst = sb + base + ch*8192u + SWZ((uint32_t)(row*128 + dc8*2));
            cp_async16(dst, src + ((size_t)(bb + ks0 + row)*NHEADS + h)*QKHD + ch*64 + dc8);
        }
#pragma unroll
        for (int i = 0; i < 8; i++) {
            int idx = tid + i*256;
            int cidx = idx;
            const __nv_bfloat16* src;
            uint32_t base;
            if (cidx < 1024) { src = vfh; base = (uint32_t)FL_VH; }
            else             { src = vfl; base = (uint32_t)FL_VL; cidx -= 1024; }
            int row = cidx >> 4;
            int c = cidx & 15;
            int ch = c >> 3;
            int dc8 = (c & 7) * 8;
            uint32_t dst = sb + base + ch*8192u + SWZ((uint32_t)(row*128 + dc8*2));
            cp_async16(dst, src + ((size_t)(bb + ks0 + row)*NHEADS + h)*VHD + ch*64 + dc8);
        }
        CP_COMMIT();
        CP_WAIT0();                        // Q (kt=0) + K + V all arrived
        __syncthreads();

        if (ks0 > s0 + wrow + 15) continue;   // fully-masked tile for this warp

        // ---- S = Q K^T ----
        float sc[8][4];
#pragma unroll
        for (int nt = 0; nt < 8; nt++)
#pragma unroll
            for (int q = 0; q < 4; q++) sc[nt][q] = 0.f;

#pragma unroll
        for (int ks = 0; ks < 12; ks++) {
            int ch = ks >> 2;
            uint32_t kb = (uint32_t)((ks & 3) * 32);
            uint32_t ah[4], al[4];
            {
                uint32_t row = wrow + (lane & 15);
                uint32_t off = SWZ(row*128u + kb + ((lane >> 4) << 4));
                ldmatrix_x4(ah, sb + FL_QH + ch*16384 + off);
                ldmatrix_x4(al, sb + FL_QL + ch*16384 + off);
            }
            uint32_t bh[16], bl[16];
#pragma unroll
            for (int ng = 0; ng < 4; ng++) {
                uint32_t nrow = ng*16 + ((lane >> 4) << 3) + (lane & 7);
                uint32_t off = SWZ(nrow*128u + kb + (((lane >> 3) & 1) << 4));
                ldmatrix_x4(&bh[ng*4], sb + FL_KH + ch*8192 + off);
                ldmatrix_x4(&bl[ng*4], sb + FL_KL + ch*8192 + off);
            }
#pragma unroll
            for (int nt = 0; nt < 8; nt++) {
                mma_bf16(sc[nt], ah, bh[nt*2], bh[nt*2+1]);
                mma_bf16(sc[nt], ah, bl[nt*2], bl[nt*2+1]);
                mma_bf16(sc[nt], al, bh[nt*2], bh[nt*2+1]);
            }
        }

        if (ks0 + 63 > s0 + wrow) {
#pragma unroll
            for (int nt = 0; nt < 8; nt++) {
                int colg = ks0 + nt*8 + (lane & 3)*2;
                if (colg     > rg0) sc[nt][0] = -1e30f;
                if (colg + 1 > rg0) sc[nt][1] = -1e30f;
                if (colg     > rg1) sc[nt][2] = -1e30f;
                if (colg + 1 > rg1) sc[nt][3] = -1e30f;
            }
        }

        // ---- online softmax ----
        float mx0 = -1e30f, mx1 = -1e30f;
#pragma unroll
        for (int nt = 0; nt < 8; nt++) {
            mx0 = fmaxf(mx0, fmaxf(sc[nt][0], sc[nt][1]));
            mx1 = fmaxf(mx1, fmaxf(sc[nt][2], sc[nt][3]));
        }
        mx0 = fmaxf(mx0, __shfl_xor_sync(0xffffffffu, mx0, 1));
        mx0 = fmaxf(mx0, __shfl_xor_sync(0xffffffffu, mx0, 2));
        mx1 = fmaxf(mx1, __shfl_xor_sync(0xffffffffu, mx1, 1));
        mx1 = fmaxf(mx1, __shfl_xor_sync(0xffffffffu, mx1, 2));
        float mn0 = fmaxf(m0, mx0), mn1 = fmaxf(m1, mx1);
        float a0 = __expf(m0 - mn0), a1 = __expf(m1 - mn1);
        m0 = mn0; m1 = mn1;
        float rs0 = 0.f, rs1 = 0.f;
#pragma unroll
        for (int nt = 0; nt < 8; nt++) {
            sc[nt][0] = __expf(sc[nt][0] - mn0); rs0 += sc[nt][0];
            sc[nt][1] = __expf(sc[nt][1] - mn0); rs0 += sc[nt][1];
            sc[nt][2] = __expf(sc[nt][2] - mn1); rs1 += sc[nt][2];
            sc[nt][3] = __expf(sc[nt][3] - mn1); rs1 += sc[nt][3];
        }
        rs0 += __shfl_xor_sync(0xffffffffu, rs0, 1);
        rs0 += __shfl_xor_sync(0xffffffffu, rs0, 2);
        rs1 += __shfl_xor_sync(0xffffffffu, rs1, 1);
        rs1 += __shfl_xor_sync(0xffffffffu, rs1, 2);
        l0 = l0*a0 + rs0;
        l1 = l1*a1 + rs1;
#pragma unroll
        for (int nt = 0; nt < 16; nt++) {
            oc[nt][0] *= a0; oc[nt][1] *= a0;
            oc[nt][2] *= a1; oc[nt][3] *= a1;
        }

        // ---- O += P V (P in registers; no barrier needed) ----
#pragma unroll
        for (int kp = 0; kp < 4; kp++) {
            uint32_t ph[4], pl[4];
            {
                float p0 = sc[2*kp][0],  p1 = sc[2*kp][1];
                float p2 = sc[2*kp][2],  p3 = sc[2*kp][3];
                float p4 = sc[2*kp+1][0], p5 = sc[2*kp+1][1];
                float p6 = sc[2*kp+1][2], p7 = sc[2*kp+1][3];
                ph[0] = pack_bf16x2(p0, p1);
                ph[1] = pack_bf16x2(p2, p3);
                ph[2] = pack_bf16x2(p4, p5);
                ph[3] = pack_bf16x2(p6, p7);
                __nv_bfloat162* hp;
                hp = reinterpret_cast<__nv_bfloat162*>(&ph[0]);
                pl[0] = pack_bf16x2(p0 - __bfloat162float(hp->x), p1 - __bfloat162float(hp->y));
                hp = reinterpret_cast<__nv_bfloat162*>(&ph[1]);
                pl[1] = pack_bf16x2(p2 - __bfloat162float(hp->x), p3 - __bfloat162float(hp->y));
                hp = reinterpret_cast<__nv_bfloat162*>(&ph[2]);
                pl[2] = pack_bf16x2(p4 - __bfloat162float(hp->x), p5 - __bfloat162float(hp->y));
                hp = reinterpret_cast<__nv_bfloat162*>(&ph[3]);
                pl[3] = pack_bf16x2(p6 - __bfloat162float(hp->x), p7 - __bfloat162float(hp->y));
            }
#pragma unroll
            for (int ng = 0; ng < 8; ng++) {
                int ch = ng >> 2;
                uint32_t n0 = (uint32_t)((ng & 3)*16) + ((lane >> 4) << 3);
                uint32_t krow = (uint32_t)(kp*16) + (lane & 15);
                uint32_t off = SWZ(krow*128u + n0*2u);
                uint32_t vh[4], vl[4];
                ldmatrix_x4_trans(vh, sb + FL_VH + ch*8192 + off);
                ldmatrix_x4_trans(vl, sb + FL_VL + ch*8192 + off);
                mma_bf16(oc[ng*2],   ph, vh[0], vh[1]);
                mma_bf16(oc[ng*2],   ph, vl[0], vl[1]);
                mma_bf16(oc[ng*2],   pl, vh[0], vh[1]);
                mma_bf16(oc[ng*2+1], ph, vh[2], vh[3]);
                mma_bf16(oc[ng*2+1], ph, vl[2], vl[3]);
                mma_bf16(oc[ng*2+1], pl, vh[2], vh[3]);
            }
        }
    }

    float inv0 = 1.f / l0, inv1 = 1.f / l1;
    int row0 = bb + s0 + wrow + (lane >> 2);
    int row1 = row0 + 8;
#pragma unroll
    for (int nt = 0; nt < 16; nt++) {
        int col = h*128 + nt*8 + (lane & 3)*2;
        float o0 = oc[nt][0]*inv0, o1 = oc[nt][1]*inv0;
        float o2 = oc[nt][2]*inv1, o3 = oc[nt][3]*inv1;
        uint32_t h0 = pack_bf16x2(o0, o1);
        __nv_bfloat162 hv0 = *reinterpret_cast<__nv_bfloat162*>(&h0);
        uint32_t l0p = pack_bf16x2(o0 - __bfloat162float(hv0.x), o1 - __bfloat162float(hv0.y));
        uint32_t h1 = pack_bf16x2(o2, o3);
        __nv_bfloat162 hv1 = *reinterpret_cast<__nv_bfloat162*>(&h1);
        uint32_t l1p = pack_bf16x2(o2 - __bfloat162float(hv1.x), o3 - __bfloat162float(hv1.y));
        *reinterpret_cast<uint32_t*>(atth + (size_t)row0*2048 + col) = h0;
        *reinterpret_cast<uint32_t*>(attl + (size_t)row0*2048 + col) = l0p;
        *reinterpret_cast<uint32_t*>(atth + (size_t)row1*2048 + col) = h1;
        *reinterpret_cast<uint32_t*>(attl + (size_t)row1*2048 + col) = l1p;
    }
}

// ---------------- host launcher ----------------
extern "C" void kernel_launch(void* const* d_in, const int* in_sizes, int n_in,
                              void* d_out, int out_size)
{
    const float* x      = (const float*)d_in[0];
    const float* wqa    = (const float*)d_in[1];
    const float* wqa_b  = (const float*)d_in[2];
    const float* qnw    = (const float*)d_in[3];
    const float* wqb    = (const float*)d_in[4];
    const float* wqb_b  = (const float*)d_in[5];
    const float* wkva   = (const float*)d_in[6];
    const float* wkva_b = (const float*)d_in[7];
    const float* kvnw   = (const float*)d_in[8];
    const float* wkvb   = (const float*)d_in[9];
    const float* wkvb_b = (const float*)d_in[10];
    const float* wo     = (const float*)d_in[11];
    const float* wo_b   = (const float*)d_in[12];
    float* out = (float*)d_out;

    float *qkv, *bqkv;
    cudaGetSymbolAddress((void**)&qkv, g_qkv);
    cudaGetSymbolAddress((void**)&bqkv, g_bqkv);
    __nv_bfloat16 *xh,*xl,*qah,*qal,*kvch,*kvcl,*atth,*attl;
    __nv_bfloat16 *wqkvh,*wqkvl,*wqbh,*wqbl,*wkvbh,*wkvbl,*woh,*wol;
    __nv_bfloat16 *kfh,*kfl,*vfh,*vfl,*qfh,*qfl;
    cudaGetSymbolAddress((void**)&xh, g_xh);   cudaGetSymbolAddress((void**)&xl, g_xl);
    cudaGetSymbolAddress((void**)&qah, g_qah); cudaGetSymbolAddress((void**)&qal, g_qal);
    cudaGetSymbolAddress((void**)&kvch, g_kvch); cudaGetSymbolAddress((void**)&kvcl, g_kvcl);
    cudaGetSymbolAddress((void**)&atth, g_atth); cudaGetSymbolAddress((void**)&attl, g_attl);
    cudaGetSymbolAddress((void**)&wqkvh, g_wqkvh); cudaGetSymbolAddress((void**)&wqkvl, g_wqkvl);
    cudaGetSymbolAddress((void**)&wqbh, g_wqbh); cudaGetSymbolAddress((void**)&wqbl, g_wqbl);
    cudaGetSymbolAddress((void**)&wkvbh, g_wkvbh); cudaGetSymbolAddress((void**)&wkvbl, g_wkvbl);
    cudaGetSymbolAddress((void**)&woh, g_woh); cudaGetSymbolAddress((void**)&wol, g_wol);
    cudaGetSymbolAddress((void**)&kfh, g_kfh); cudaGetSymbolAddress((void**)&kfl, g_kfl);
    cudaGetSymbolAddress((void**)&vfh, g_vfh); cudaGetSymbolAddress((void**)&vfl, g_vfl);
    cudaGetSymbolAddress((void**)&qfh, g_qfh); cudaGetSymbolAddress((void**)&qfl, g_qfl);

    cudaFuncSetAttribute(flash_mma, cudaFuncAttributeMaxDynamicSharedMemorySize, FL_SMEM + 128);
    cudaFuncSetAttribute(gemm_bf, cudaFuncAttributeMaxDynamicSharedMemorySize, GB_SMEM);
    cudaFuncSetAttribute(gemm_bf_q, cudaFuncAttributeMaxDynamicSharedMemorySize, GB_SMEM);
    cudaFuncSetAttribute(gemm_bf_kv, cudaFuncAttributeMaxDynamicSharedMemorySize, GB_SMEM);

    dim3 t256(256);

    // 1. fused conversions (weights + x + bias combine + rope tables)
    cvt_all<<<CVT_TOTAL, t256>>>(wqa, wkva, wqb, wkvb, wo, x, wqa_b, wkva_b);
    // 2. merged qkv = x @ [wq_a; wkv_a]^T + b
    gemm_bf<<<dim3((QKVW+127)/128, ROWS/128), t256, GB_SMEM>>>(xh, xl, DIMX, wqkvh, wqkvl, DIMX, bqkv, qkv, QKVW, QKVW, DIMX);
    // 3. rmsnorm q + kv_c + k_pe rope (one launch)
    rmsnorm_both<<<dim3(ROWS, 3), t256>>>(qkv, qah, qal, kvch, kvcl, qnw, kvnw, kfh, kfl);
    // 4. q_b GEMM with fused RoPE(table) + scale + bf16 plane epilogue
    gemm_bf_q<<<dim3(3072/128, ROWS/128), t256, GB_SMEM>>>(qah, qal, QLORA, wqbh, wqbl, QLORA, wqb_b, qfh, qfl, 3072, QLORA);
    // 5. kvb GEMM with fused bf16 plane epilogue
    gemm_bf_kv<<<dim3(4096/128, ROWS/128), t256, GB_SMEM>>>(kvch, kvcl, KVLORA, wkvbh, wkvbl, KVLORA, wkvb_b, kfh, kfl, vfh, vfl, 4096, KVLORA);
    // 6. flash (all operands via cp.async bf16 planes)
    flash_mma<<<dim3(SEQL/128, NHEADS, BSZ), t256, FL_SMEM + 128>>>(qfh, qfl, kfh, kfl, vfh, vfl, atth, attl);
    // 7. out
    gemm_bf<<<dim3(2048/128, ROWS/128), t256, GB_SMEM>>>(atth, attl, 2048, woh, wol, 2048, wo_b, out, 2048, 2048, DIMX);
}

// round 17
// speedup vs baseline: 1.0094x; 1.0047x over previous
#include <cuda_runtime.h>
#include <cuda_bf16.h>
#include <cstdint>
#include <math.h>

#define SEQL   2048
#define BSZ    2
#define ROWS   (BSZ*SEQL)          // 4096
#define DIMX   2048
#define QLORA  1536
#define KVLORA 512
#define NHEADS 16
#define QKHD   192
#define NOPE_D 128
#define ROPE_D 64
#define VHD    128
#define QKVW   2112                // 1536 q + 512 kv_c + 64 k_pe
#define QSCALE 0.07216878364870323f

// ---------------- scratch (static device globals; no allocation) ----------------
__device__ float g_qkv[ROWS*QKVW];
__device__ float g_bqkv[QKVW];
__device__ float g_ropec[SEQL*32], g_ropes[SEQL*32];

__device__ __nv_bfloat16 g_xh  [ROWS*DIMX],   g_xl  [ROWS*DIMX];
__device__ __nv_bfloat16 g_qah [ROWS*QLORA],  g_qal [ROWS*QLORA];
__device__ __nv_bfloat16 g_kvch[ROWS*KVLORA], g_kvcl[ROWS*KVLORA];
__device__ __nv_bfloat16 g_atth[ROWS*2048],   g_attl[ROWS*2048];
__device__ __nv_bfloat16 g_wqkvh[QKVW*DIMX],  g_wqkvl[QKVW*DIMX];
__device__ __nv_bfloat16 g_wqbh[3072*QLORA],  g_wqbl[3072*QLORA];
__device__ __nv_bfloat16 g_wkvbh[4096*KVLORA],g_wkvbl[4096*KVLORA];
__device__ __nv_bfloat16 g_woh [DIMX*2048],   g_wol [DIMX*2048];
__device__ __nv_bfloat16 g_kfh[ROWS*NHEADS*QKHD], g_kfl[ROWS*NHEADS*QKHD];
__device__ __nv_bfloat16 g_vfh[ROWS*NHEADS*VHD],  g_vfl[ROWS*NHEADS*VHD];
__device__ __nv_bfloat16 g_qfh[ROWS*NHEADS*QKHD], g_qfl[ROWS*NHEADS*QKHD];

__device__ __forceinline__ uint32_t smem_to_u32(const void* p) {
    uint32_t a;
    asm("{ .reg .u64 t; cvta.to.shared.u64 t, %1; cvt.u32.u64 %0, t; }" : "=r"(a) : "l"(p));
    return a;
}
#define SWZ(x)   ((x) ^ (((x) >> 3) & 0x70))
#define SWZ64(x) ((x) ^ (((x) >> 3) & 0x30))

__device__ __forceinline__ void ldmatrix_x4(uint32_t* r, uint32_t addr) {
    asm volatile("ldmatrix.sync.aligned.m8n8.x4.shared.b16 {%0,%1,%2,%3}, [%4];"
        : "=r"(r[0]), "=r"(r[1]), "=r"(r[2]), "=r"(r[3]) : "r"(addr));
}
__device__ __forceinline__ void ldmatrix_x4_trans(uint32_t* r, uint32_t addr) {
    asm volatile("ldmatrix.sync.aligned.m8n8.x4.trans.shared.b16 {%0,%1,%2,%3}, [%4];"
        : "=r"(r[0]), "=r"(r[1]), "=r"(r[2]), "=r"(r[3]) : "r"(addr));
}
__device__ __forceinline__ void mma_bf16(float* c, const uint32_t* a, uint32_t b0, uint32_t b1) {
    asm volatile(
        "mma.sync.aligned.m16n8k16.row.col.f32.bf16.bf16.f32 "
        "{%0,%1,%2,%3}, {%4,%5,%6,%7}, {%8,%9}, {%0,%1,%2,%3};"
        : "+f"(c[0]), "+f"(c[1]), "+f"(c[2]), "+f"(c[3])
        : "r"(a[0]), "r"(a[1]), "r"(a[2]), "r"(a[3]), "r"(b0), "r"(b1));
}
__device__ __forceinline__ uint32_t pack_bf16x2(float lo, float hi) {
    __nv_bfloat162 h = __floats2bfloat162_rn(lo, hi);
    return *reinterpret_cast<uint32_t*>(&h);
}
__device__ __forceinline__ void cp_async16(uint32_t dst, const void* src) {
    asm volatile("cp.async.cg.shared.global [%0], [%1], 16;" :: "r"(dst), "l"(src));
}
#define CP_COMMIT() asm volatile("cp.async.commit_group;" ::: "memory")
#define CP_WAIT1()  asm volatile("cp.async.wait_group 1;" ::: "memory")
#define CP_WAIT0()  asm volatile("cp.async.wait_group 0;" ::: "memory")

// ============ fused converter: weights + x (hi/lo) + bias combine + rope tables ============
#define CVT_BLKS 11584
#define CVT_TOTAL (CVT_BLKS + 3 + 256)

__global__ __launch_bounds__(256)
void cvt_all(const float* __restrict__ wqa, const float* __restrict__ wkva,
             const float* __restrict__ wqb, const float* __restrict__ wkvb,
             const float* __restrict__ wo,  const float* __restrict__ x,
             const float* __restrict__ bq,  const float* __restrict__ bkv)
{
    int blk = blockIdx.x;
    if (blk >= CVT_BLKS) {
        int ex = blk - CVT_BLKS;
        if (ex < 3) {
            int i = ex * 256 + threadIdx.x;
            if (i < QKVW) g_bqkv[i] = (i < QLORA) ? bq[i] : bkv[i - QLORA];
        } else {
            int i = (ex - 3) * 256 + threadIdx.x;
            int pos = i >> 5, d = i & 31;
            float ang = (float)pos * powf(10000.f, -(float)d * (1.f/32.f));
            float sn, c;
            sincosf(ang, &sn, &c);
            g_ropec[i] = c;
            g_ropes[i] = sn;
        }
        return;
    }
    const float* src;
    __nv_bfloat16 *hi, *lo;
    int base;
    if (blk < 1536)      { src = wqa;  hi = g_wqkvh; lo = g_wqkvl; base = blk; }
    else if (blk < 2112) { src = wkva; hi = g_wqkvh + (size_t)QLORA*DIMX;
                           lo = g_wqkvl + (size_t)QLORA*DIMX; base = blk - 1536; }
    else if (blk < 4416) { src = wqb;  hi = g_wqbh;  lo = g_wqbl;  base = blk - 2112; }
    else if (blk < 5440) { src = wkvb; hi = g_wkvbh; lo = g_wkvbl; base = blk - 4416; }
    else if (blk < 7488) { src = wo;   hi = g_woh;   lo = g_wol;   base = blk - 5440; }
    else                 { src = x;    hi = g_xh;    lo = g_xl;    base = blk - 7488; }

    size_t i0 = (size_t)base * 2048 + threadIdx.x * 4;
#pragma unroll
    for (int rep = 0; rep < 2; rep++) {
        size_t i = i0 + rep * 1024;
        float4 v = *reinterpret_cast<const float4*>(src + i);
        __nv_bfloat162 h01 = __floats2bfloat162_rn(v.x, v.y);
        __nv_bfloat162 h23 = __floats2bfloat162_rn(v.z, v.w);
        __nv_bfloat162 l01 = __floats2bfloat162_rn(v.x - __bfloat162float(h01.x),
                                                   v.y - __bfloat162float(h01.y));
        __nv_bfloat162 l23 = __floats2bfloat162_rn(v.z - __bfloat162float(h23.x),
                                                   v.w - __bfloat162float(h23.y));
        *reinterpret_cast<uint2*>(hi + i) =
            make_uint2(*reinterpret_cast<uint32_t*>(&h01), *reinterpret_cast<uint32_t*>(&h23));
        *reinterpret_cast<uint2*>(lo + i) =
            make_uint2(*reinterpret_cast<uint32_t*>(&l01), *reinterpret_cast<uint32_t*>(&l23));
    }
}

// ============ cp.async 3-stage split-bf16 HMMA GEMM, CTA 128x128, K-tile 32 ============
// Single barrier per K-tile: WAIT1 -> sync -> issue(kt+2) -> commit -> compute.
// Safe: at sync of iter kt all warps finished reading stage (kt-1)%3 == (kt+2)%3.
#define GB_STAGE 32768
#define GB_SMEM  (3*GB_STAGE + 128)

#define GB_MAINLOOP(ACCDECL)                                                    \
    extern __shared__ char smraw[];                                             \
    uint32_t sb0 = smem_to_u32(smraw);                                          \
    uint32_t sb = (sb0 + 127u) & ~127u;                                         \
    const int tid  = threadIdx.x;                                               \
    const int lane = tid & 31;                                                  \
    const int wid  = tid >> 5;                                                  \
    const int bm = blockIdx.y * 128;                                            \
    const int bn = blockIdx.x * 128;                                            \
    const int wm = (wid & 3) * 32;                                              \
    const int wn = (wid >> 2) * 64;                                             \
    const int nk = K >> 5;                                                      \
    ACCDECL                                                                     \
    GB_ISSUE(0); CP_COMMIT();                                                   \
    if (nk > 1) { GB_ISSUE(1); }                                                \
    CP_COMMIT();                                                                \
    for (int kt = 0; kt < nk; kt++) {                                           \
        CP_WAIT1();                                                             \
        __syncthreads();                                                        \
        if (kt + 2 < nk) { GB_ISSUE(kt + 2); }                                  \
        CP_COMMIT();                                                            \
        const uint32_t baseA = sb + (uint32_t)(kt % 3) * GB_STAGE;              \
        const uint32_t baseB = baseA + 16384u;                                  \
        _Pragma("unroll")                                                       \
        for (int k16 = 0; k16 < 2; k16++) {                                     \
            uint32_t ah[2][4], al[2][4];                                        \
            _Pragma("unroll")                                                   \
            for (int mt = 0; mt < 2; mt++) {                                    \
                uint32_t row = wm + mt*16 + (lane & 15);                        \
                uint32_t off = SWZ64(row*64u + (uint32_t)(k16*32) + ((lane >> 4) << 4)); \
                ldmatrix_x4(ah[mt], baseA + off);                               \
                ldmatrix_x4(al[mt], baseA + 8192u + off);                       \
            }                                                                   \
            _Pragma("unroll")                                                   \
            for (int ng = 0; ng < 4; ng++) {                                    \
                uint32_t bh[4], bl[4];                                          \
                uint32_t nrow = wn + ng*16 + ((lane >> 4) << 3) + (lane & 7);   \
                uint32_t off = SWZ64(nrow*64u + (uint32_t)(k16*32) + (((lane >> 3) & 1) << 4)); \
                ldmatrix_x4(bh, baseB + off);                                   \
                ldmatrix_x4(bl, baseB + 8192u + off);                           \
                _Pragma("unroll")                                               \
                for (int mt = 0; mt < 2; mt++) {                                \
                    float* a0 = acc[mt][2*ng];                                  \
                    float* a1 = acc[mt][2*ng+1];                                \
                    mma_bf16(a0, ah[mt], bh[0], bh[1]);                         \
                    mma_bf16(a0, ah[mt], bl[0], bl[1]);                         \
                    mma_bf16(a0, al[mt], bh[0], bh[1]);                         \
                    mma_bf16(a1, ah[mt], bh[2], bh[3]);                         \
                    mma_bf16(a1, ah[mt], bl[2], bl[3]);                         \
                    mma_bf16(a1, al[mt], bh[2], bh[3]);                         \
                }                                                               \
            }                                                                   \
        }                                                                       \
    }

#define GB_ACCDECL \
    float acc[2][8][4]; \
    _Pragma("unroll") \
    for (int mt = 0; mt < 2; mt++) \
        _Pragma("unroll") \
        for (int nt = 0; nt < 8; nt++) \
            _Pragma("unroll") \
            for (int q = 0; q < 4; q++) acc[mt][nt][q] = 0.f;

#define GB_ISSUE(kt_) do {                                                      \
        const uint32_t stb = sb + (uint32_t)((kt_) % 3) * GB_STAGE;             \
        const int k0_ = (kt_) << 5;                                             \
        _Pragma("unroll")                                                       \
        for (int i = 0; i < 8; i++) {                                           \
            const int plane = i >> 1;                                           \
            const int idx = ((i & 1) << 8) + tid;                               \
            const int r = idx >> 2;                                             \
            const int c = idx & 3;                                              \
            uint32_t dst = stb + (uint32_t)plane*8192u                          \
                         + SWZ64((uint32_t)(r*64 + c*16));                      \
            const __nv_bfloat16* srcp;                                          \
            if (plane == 0)      srcp = Ah + (size_t)(bm + r)*lda + k0_ + c*8;  \
            else if (plane == 1) srcp = Al + (size_t)(bm + r)*lda + k0_ + c*8;  \
            else {                                                              \
                int rr = bn + r; if (rr >= Nn) rr = Nn - 1;                     \
                srcp = (plane == 2 ? Bh : Bl) + (size_t)rr*ldw + k0_ + c*8;     \
            }                                                                   \
            cp_async16(dst, srcp);                                              \
        }                                                                       \
    } while (0)

__global__ __launch_bounds__(256, 2)
void gemm_bf(const __nv_bfloat16* __restrict__ Ah, const __nv_bfloat16* __restrict__ Al, int lda,
             const __nv_bfloat16* __restrict__ Bh, const __nv_bfloat16* __restrict__ Bl, int ldw,
             const float* __restrict__ bias,
             float* __restrict__ C, int ldc,
             int Nn, int K)
{
    GB_MAINLOOP(GB_ACCDECL)

#pragma unroll
    for (int nt = 0; nt < 8; nt++) {
        int col = bn + wn + nt*8 + (lane & 3)*2;
        if (col >= Nn) continue;
        float bx = bias[col], by = bias[col+1];
#pragma unroll
        for (int mt = 0; mt < 2; mt++) {
            int row = bm + wm + mt*16 + (lane >> 2);
            *reinterpret_cast<float2*>(C + (size_t)row*ldc + col) =
                make_float2(acc[mt][nt][0] + bx, acc[mt][nt][1] + by);
            *reinterpret_cast<float2*>(C + (size_t)(row+8)*ldc + col) =
                make_float2(acc[mt][nt][2] + bx, acc[mt][nt][3] + by);
        }
    }
}

// q_b GEMM: epilogue applies RoPE (table-based) + scale, writes head-major q planes
__global__ __launch_bounds__(256, 2)
void gemm_bf_q(const __nv_bfloat16* __restrict__ Ah, const __nv_bfloat16* __restrict__ Al, int lda,
               const __nv_bfloat16* __restrict__ Bh, const __nv_bfloat16* __restrict__ Bl, int ldw,
               const float* __restrict__ bias,
               __nv_bfloat16* __restrict__ qfh, __nv_bfloat16* __restrict__ qfl,
               int Nn, int K)
{
    GB_MAINLOOP(GB_ACCDECL)

    const bool ispe = ((((bn + wn) >> 6) % 3) == 2);
    if (!ispe) {
#pragma unroll
        for (int nt = 0; nt < 8; nt++) {
            int col = bn + wn + nt*8 + (lane & 3)*2;
            float bx = bias[col], by = bias[col+1];
            int hh = col / 192;
            int d  = col - hh*192;
#pragma unroll
            for (int mt = 0; mt < 2; mt++)
#pragma unroll
                for (int half = 0; half < 2; half++) {
                    int r = bm + wm + mt*16 + (lane >> 2) + half*8;
                    float v0 = (acc[mt][nt][half*2+0] + bx) * QSCALE;
                    float v1 = (acc[mt][nt][half*2+1] + by) * QSCALE;
                    uint32_t hpk = pack_bf16x2(v0, v1);
                    __nv_bfloat162 hv = *reinterpret_cast<__nv_bfloat162*>(&hpk);
                    uint32_t lpk = pack_bf16x2(v0 - __bfloat162float(hv.x),
                                               v1 - __bfloat162float(hv.y));
                    size_t idx = ((size_t)r*NHEADS + hh)*QKHD + d;
                    *reinterpret_cast<uint32_t*>(qfh + idx) = hpk;
                    *reinterpret_cast<uint32_t*>(qfl + idx) = lpk;
                }
        }
    } else {
#pragma unroll
        for (int nt = 0; nt < 4; nt++) {
            int colA = bn + wn + nt*8 + (lane & 3)*2;
            int hh = colA / 192;
            int dA = colA - hh*192;
            int dd0 = dA - 128;
            float bxA = bias[colA],    byA = bias[colA+1];
            float bxB = bias[colA+32], byB = bias[colA+33];
#pragma unroll
            for (int mt = 0; mt < 2; mt++)
#pragma unroll
                for (int half = 0; half < 2; half++) {
                    int r = bm + wm + mt*16 + (lane >> 2) + half*8;
                    int tb = (r & (SEQL-1))*32 + dd0;
                    float c0 = g_ropec[tb],   s0 = g_ropes[tb];
                    float c1 = g_ropec[tb+1], s1 = g_ropes[tb+1];
                    float x10 = acc[mt][nt][half*2+0]   + bxA;
                    float x11 = acc[mt][nt][half*2+1]   + byA;
                    float x20 = acc[mt][nt+4][half*2+0] + bxB;
                    float x21 = acc[mt][nt+4][half*2+1] + byB;
                    float rA0 = (x10*c0 - x20*s0) * QSCALE;
                    float rA1 = (x11*c1 - x21*s1) * QSCALE;
                    float rB0 = (x20*c0 + x10*s0) * QSCALE;
                    float rB1 = (x21*c1 + x11*s1) * QSCALE;
                    size_t idx = ((size_t)r*NHEADS + hh)*QKHD + dA;
                    uint32_t hA = pack_bf16x2(rA0, rA1);
                    __nv_bfloat162 hva = *reinterpret_cast<__nv_bfloat162*>(&hA);
                    uint32_t lA = pack_bf16x2(rA0 - __bfloat162float(hva.x),
                                              rA1 - __bfloat162float(hva.y));
                    uint32_t hB = pack_bf16x2(rB0, rB1);
                    __nv_bfloat162 hvb = *reinterpret_cast<__nv_bfloat162*>(&hB);
                    uint32_t lB = pack_bf16x2(rB0 - __bfloat162float(hvb.x),
                                              rB1 - __bfloat162float(hvb.y));
                    *reinterpret_cast<uint32_t*>(qfh + idx)      = hA;
                    *reinterpret_cast<uint32_t*>(qfl + idx)      = lA;
                    *reinterpret_cast<uint32_t*>(qfh + idx + 32) = hB;
                    *reinterpret_cast<uint32_t*>(qfl + idx + 32) = lB;
                }
        }
    }
}

// kvb GEMM: epilogue converts directly into head-major bf16 hi/lo K-nope / V planes
__global__ __launch_bounds__(256, 2)
void gemm_bf_kv(const __nv_bfloat16* __restrict__ Ah, const __nv_bfloat16* __restrict__ Al, int lda,
                const __nv_bfloat16* __restrict__ Bh, const __nv_bfloat16* __restrict__ Bl, int ldw,
                const float* __restrict__ bias,
                __nv_bfloat16* __restrict__ kfh, __nv_bfloat16* __restrict__ kfl,
                __nv_bfloat16* __restrict__ vfh, __nv_bfloat16* __restrict__ vfl,
                int Nn, int K)
{
    GB_MAINLOOP(GB_ACCDECL)

#pragma unroll
    for (int nt = 0; nt < 8; nt++) {
        int col = bn + wn + nt*8 + (lane & 3)*2;
        float bx = bias[col], by = bias[col+1];
        int hh = col >> 8;
        int d  = col & 255;
#pragma unroll
        for (int mt = 0; mt < 2; mt++) {
            int row = bm + wm + mt*16 + (lane >> 2);
#pragma unroll
            for (int half = 0; half < 2; half++) {
                float v0 = acc[mt][nt][half*2+0] + bx;
                float v1 = acc[mt][nt][half*2+1] + by;
                int r = row + half*8;
                uint32_t hpk = pack_bf16x2(v0, v1);
                __nv_bfloat162 hv = *reinterpret_cast<__nv_bfloat162*>(&hpk);
                uint32_t lpk = pack_bf16x2(v0 - __bfloat162float(hv.x),
                                           v1 - __bfloat162float(hv.y));
                if (d < 128) {
                    size_t idx = ((size_t)r*NHEADS + hh)*QKHD + d;
                    *reinterpret_cast<uint32_t*>(kfh + idx) = hpk;
                    *reinterpret_cast<uint32_t*>(kfl + idx) = lpk;
                } else {
                    size_t idx = ((size_t)r*NHEADS + hh)*VHD + (d - 128);
                    *reinterpret_cast<uint32_t*>(vfh + idx) = hpk;
                    *reinterpret_cast<uint32_t*>(vfl + idx) = lpk;
                }
            }
        }
    }
}

// ---------------- merged RMSNorm (q, kv_c) + k_pe rope in one launch ----------------
__global__ __launch_bounds__(256)
void rmsnorm_both(const float* __restrict__ qkv,
                  __nv_bfloat16* __restrict__ qh, __nv_bfloat16* __restrict__ ql,
                  __nv_bfloat16* __restrict__ kh, __nv_bfloat16* __restrict__ kl,
                  const float* __restrict__ qw, const float* __restrict__ kw,
                  __nv_bfloat16* __restrict__ kfh, __nv_bfloat16* __restrict__ kfl)
{
    int row = blockIdx.x;
    int which = blockIdx.y;
    if (which == 2) {
        int d = threadIdx.x;
        if (d < 32) {
            int s = row & (SEQL - 1);
            float c = g_ropec[s*32 + d], sn = g_ropes[s*32 + d];
            const float* base = qkv + (size_t)row*QKVW + 2048;
            float x1 = base[d], x2 = base[d+32];
            float r1 = x1*c - x2*sn;
            float r2 = x2*c + x1*sn;
            __nv_bfloat16 h1 = __float2bfloat16_rn(r1);
            __nv_bfloat16 l1 = __float2bfloat16_rn(r1 - __bfloat162float(h1));
            __nv_bfloat16 h2 = __float2bfloat16_rn(r2);
            __nv_bfloat16 l2 = __float2bfloat16_rn(r2 - __bfloat162float(h2));
#pragma unroll
            for (int hh = 0; hh < NHEADS; hh++) {
                size_t idx = ((size_t)row*NHEADS + hh)*QKHD + 128 + d;
                kfh[idx]      = h1;
                kfl[idx]      = l1;
                kfh[idx + 32] = h2;
                kfl[idx + 32] = l2;
            }
        }
        return;
    }
    int width = which ? KVLORA : QLORA;
    const float* s = qkv + (size_t)row * QKVW + (which ? QLORA : 0);
    const float* w = which ? kw : qw;
    __nv_bfloat16* dh = which ? (kh + (size_t)row*KVLORA) : (qh + (size_t)row*QLORA);
    __nv_bfloat16* dl = which ? (kl + (size_t)row*KVLORA) : (ql + (size_t)row*QLORA);

    float ss = 0.f;
    for (int c = threadIdx.x; c < width; c += blockDim.x) { float v = s[c]; ss += v*v; }

    __shared__ float red[8];
#pragma unroll
    for (int off = 16; off; off >>= 1) ss += __shfl_xor_sync(0xffffffffu, ss, off);
    int warp = threadIdx.x >> 5;
    if ((threadIdx.x & 31) == 0) red[warp] = ss;
    __syncthreads();
    if (warp == 0) {
        float v = (threadIdx.x < 8) ? red[threadIdx.x] : 0.f;
#pragma unroll
        for (int off = 4; off; off >>= 1) v += __shfl_xor_sync(0xffffffffu, v, off);
        if (threadIdx.x == 0) red[0] = v;
    }
    __syncthreads();
    float scale = rsqrtf(red[0] / (float)width + 1e-6f);
    for (int c = threadIdx.x; c < width; c += blockDim.x) {
        float v = s[c] * scale * w[c];
        __nv_bfloat16 hv = __float2bfloat16_rn(v);
        dh[c] = hv;
        dl[c] = __float2bfloat16_rn(v - __bfloat162float(hv));
    }
}

// ============ Flash attention: single wait-group + 2 barriers per kt ============
#define FL_QH 0
#define FL_QL 49152
#define FL_KH 98304
#define FL_KL 122880
#define FL_VH 147456
#define FL_VL 163840
#define FL_SMEM 180224

__global__ __launch_bounds__(256, 1)
void flash_mma(const __nv_bfloat16* __restrict__ qfh, const __nv_bfloat16* __restrict__ qfl,
               const __nv_bfloat16* __restrict__ kfh, const __nv_bfloat16* __restrict__ kfl,
               const __nv_bfloat16* __restrict__ vfh, const __nv_bfloat16* __restrict__ vfl,
               __nv_bfloat16* __restrict__ atth,
               __nv_bfloat16* __restrict__ attl)
{
    extern __shared__ char smraw[];
    uint32_t sb0 = smem_to_u32(smraw);
    uint32_t sb = (sb0 + 127u) & ~127u;

    const int qt = (int)gridDim.x - 1 - (int)blockIdx.x;
    const int h  = blockIdx.y;
    const int b  = blockIdx.z;
    const int s0 = qt * 128;
    const int bb = b * SEQL;
    const int tid  = threadIdx.x;
    const int lane = tid & 31;
    const int wid  = tid >> 5;
    const int wrow = wid * 16;

#pragma unroll
    for (int i = 0; i < 24; i++) {
        int idx = tid + i*256;
        int cidx = idx;
        const __nv_bfloat16* src;
        uint32_t base;
        if (cidx < 3072) { src = qfh; base = (uint32_t)FL_QH; }
        else             { src = qfl; base = (uint32_t)FL_QL; cidx -= 3072; }
        int row = cidx / 24;
        int c = cidx - row*24;
        int ch = c >> 3;
        int dc8 = (c & 7) * 8;
        uint32_t dst = sb + base + ch*16384u + SWZ((uint32_t)(row*128 + dc8*2));
        cp_async16(dst, src + ((size_t)(bb + s0 + row)*NHEADS + h)*QKHD + ch*64 + dc8);
    }
    CP_COMMIT();

    float oc[16][4];
#pragma unroll
    for (int nt = 0; nt < 16; nt++)
#pragma unroll
        for (int q = 0; q < 4; q++) oc[nt][q] = 0.f;
    float m0 = -1e30f, m1 = -1e30f, l0 = 0.f, l1 = 0.f;

    const int rg0 = s0 + wrow + (lane >> 2);
    const int rg1 = rg0 + 8;
    const int nkt = 2*qt + 2;

    for (int kt = 0; kt < nkt; kt++) {
        if (kt > 0) __syncthreads();
        const int ks0 = kt * 64;

#pragma unroll
        for (int i = 0; i < 12; i++) {
            int idx = tid + i*256;
            int cidx = idx;
            const __nv_bfloat16* src;
            uint32_t base;
            if (cidx < 1536) { src = kfh; base = (uint32_t)FL_KH; }
            else             { src = kfl; base = (uint32_t)FL_KL; cidx -= 1536; }
            int row = cidx / 24;
            int c = cidx - row*24;
            int ch = c >> 3;
            int dc8 = (c & 7) * 8;
            uint32_t dst = sb + base + ch*8192u + SWZ((uint32_t)(row*128 + dc8*2));
            cp_async16(dst, src + ((size_t)(bb + ks0 + row)*NHEADS + h)*QKHD + ch*64 + dc8);
        }
#pragma unroll
        for (int i = 0; i < 8; i++) {
            int idx = tid + i*256;
            int cidx = idx;
            const __nv_bfloat16* src;
            uint32_t base;
            if (cidx < 1024) { src = vfh; base = (uint32_t)FL_VH; }
            else             { src = vfl; base = (uint32_t)FL_VL; cidx -= 1024; }
            int row = cidx >> 4;
            int c = cidx & 15;
            int ch = c >> 3;
            int dc8 = (c & 7) * 8;
            uint32_t dst = sb + base + ch*8192u + SWZ((uint32_t)(row*128 + dc8*2));
            cp_async16(dst, src + ((size_t)(bb + ks0 + row)*NHEADS + h)*VHD + ch*64 + dc8);
        }
        CP_COMMIT();
        CP_WAIT0();
        __syncthreads();

        if (ks0 > s0 + wrow + 15) continue;

        float sc[8][4];
#pragma unroll
        for (int nt = 0; nt < 8; nt++)
#pragma unroll
            for (int q = 0; q < 4; q++) sc[nt][q] = 0.f;

#pragma unroll
        for (int ks = 0; ks < 12; ks++) {
            int ch = ks >> 2;
            uint32_t kb = (uint32_t)((ks & 3) * 32);
            uint32_t ah[4], al[4];
            {
                uint32_t row = wrow + (lane & 15);
                uint32_t off = SWZ(row*128u + kb + ((lane >> 4) << 4));
                ldmatrix_x4(ah, sb + FL_QH + ch*16384 + off);
                ldmatrix_x4(al, sb + FL_QL + ch*16384 + off);
            }
            uint32_t bh[16], bl[16];
#pragma unroll
            for (int ng = 0; ng < 4; ng++) {
                uint32_t nrow = ng*16 + ((lane >> 4) << 3) + (lane & 7);
                uint32_t off = SWZ(nrow*128u + kb + (((lane >> 3) & 1) << 4));
                ldmatrix_x4(&bh[ng*4], sb + FL_KH + ch*8192 + off);
                ldmatrix_x4(&bl[ng*4], sb + FL_KL + ch*8192 + off);
            }
#pragma unroll
            for (int nt = 0; nt < 8; nt++) {
                mma_bf16(sc[nt], ah, bh[nt*2], bh[nt*2+1]);
                mma_bf16(sc[nt], ah, bl[nt*2], bl[nt*2+1]);
                mma_bf16(sc[nt], al, bh[nt*2], bh[nt*2+1]);
            }
        }

        if (ks0 + 63 > s0 + wrow) {
#pragma unroll
            for (int nt = 0; nt < 8; nt++) {
                int colg = ks0 + nt*8 + (lane & 3)*2;
                if (colg     > rg0) sc[nt][0] = -1e30f;
                if (colg + 1 > rg0) sc[nt][1] = -1e30f;
                if (colg     > rg1) sc[nt][2] = -1e30f;
                if (colg + 1 > rg1) sc[nt][3] = -1e30f;
            }
        }

        float mx0 = -1e30f, mx1 = -1e30f;
#pragma unroll
        for (int nt = 0; nt < 8; nt++) {
            mx0 = fmaxf(mx0, fmaxf(sc[nt][0], sc[nt][1]));
            mx1 = fmaxf(mx1, fmaxf(sc[nt][2], sc[nt][3]));
        }
        mx0 = fmaxf(mx0, __shfl_xor_sync(0xffffffffu, mx0, 1));
        mx0 = fmaxf(mx0, __shfl_xor_sync(0xffffffffu, mx0, 2));
        mx1 = fmaxf(mx1, __shfl_xor_sync(0xffffffffu, mx1, 1));
        mx1 = fmaxf(mx1, __shfl_xor_sync(0xffffffffu, mx1, 2));
        float mn0 = fmaxf(m0, mx0), mn1 = fmaxf(m1, mx1);
        float a0 = __expf(m0 - mn0), a1 = __expf(m1 - mn1);
        m0 = mn0; m1 = mn1;
        float rs0 = 0.f, rs1 = 0.f;
#pragma unroll
        for (int nt = 0; nt < 8; nt++) {
            sc[nt][0] = __expf(sc[nt][0] - mn0); rs0 += sc[nt][0];
            sc[nt][1] = __expf(sc[nt][1] - mn0); rs0 += sc[nt][1];
            sc[nt][2] = __expf(sc[nt][2] - mn1); rs1 += sc[nt][2];
            sc[nt][3] = __expf(sc[nt][3] - mn1); rs1 += sc[nt][3];
        }
        rs0 += __shfl_xor_sync(0xffffffffu, rs0, 1);
        rs0 += __shfl_xor_sync(0xffffffffu, rs0, 2);
        rs1 += __shfl_xor_sync(0xffffffffu, rs1, 1);
        rs1 += __shfl_xor_sync(0xffffffffu, rs1, 2);
        l0 = l0*a0 + rs0;
        l1 = l1*a1 + rs1;
#pragma unroll
        for (int nt = 0; nt < 16; nt++) {
            oc[nt][0] *= a0; oc[nt][1] *= a0;
            oc[nt][2] *= a1; oc[nt][3] *= a1;
        }

#pragma unroll
        for (int kp = 0; kp < 4; kp++) {
            uint32_t ph[4], pl[4];
            {
                float p0 = sc[2*kp][0],  p1 = sc[2*kp][1];
                float p2 = sc[2*kp][2],  p3 = sc[2*kp][3];
                float p4 = sc[2*kp+1][0], p5 = sc[2*kp+1][1];
                float p6 = sc[2*kp+1][2], p7 = sc[2*kp+1][3];
                ph[0] = pack_bf16x2(p0, p1);
                ph[1] = pack_bf16x2(p2, p3);
                ph[2] = pack_bf16x2(p4, p5);
                ph[3] = pack_bf16x2(p6, p7);
                __nv_bfloat162* hp;
                hp = reinterpret_cast<__nv_bfloat162*>(&ph[0]);
                pl[0] = pack_bf16x2(p0 - __bfloat162float(hp->x), p1 - __bfloat162float(hp->y));
                hp = reinterpret_cast<__nv_bfloat162*>(&ph[1]);
                pl[1] = pack_bf16x2(p2 - __bfloat162float(hp->x), p3 - __bfloat162float(hp->y));
                hp = reinterpret_cast<__nv_bfloat162*>(&ph[2]);
                pl[2] = pack_bf16x2(p4 - __bfloat162float(hp->x), p5 - __bfloat162float(hp->y));
                hp = reinterpret_cast<__nv_bfloat162*>(&ph[3]);
                pl[3] = pack_bf16x2(p6 - __bfloat162float(hp->x), p7 - __bfloat162float(hp->y));
            }
#pragma unroll
            for (int ng = 0; ng < 8; ng++) {
                int ch = ng >> 2;
                uint32_t n0 = (uint32_t)((ng & 3)*16) + ((lane >> 4) << 3);
                uint32_t krow = (uint32_t)(kp*16) + (lane & 15);
                uint32_t off = SWZ(krow*128u + n0*2u);
                uint32_t vh[4], vl[4];
                ldmatrix_x4_trans(vh, sb + FL_VH + ch*8192 + off);
                ldmatrix_x4_trans(vl, sb + FL_VL + ch*8192 + off);
                mma_bf16(oc[ng*2],   ph, vh[0], vh[1]);
                mma_bf16(oc[ng*2],   ph, vl[0], vl[1]);
                mma_bf16(oc[ng*2],   pl, vh[0], vh[1]);
                mma_bf16(oc[ng*2+1], ph, vh[2], vh[3]);
                mma_bf16(oc[ng*2+1], ph, vl[2], vl[3]);
                mma_bf16(oc[ng*2+1], pl, vh[2], vh[3]);
            }
        }
    }

    float inv0 = 1.f / l0, inv1 = 1.f / l1;
    int row0 = bb + s0 + wrow + (lane >> 2);
    int row1 = row0 + 8;
#pragma unroll
    for (int nt = 0; nt < 16; nt++) {
        int col = h*128 + nt*8 + (lane & 3)*2;
        float o0 = oc[nt][0]*inv0, o1 = oc[nt][1]*inv0;
        float o2 = oc[nt][2]*inv1, o3 = oc[nt][3]*inv1;
        uint32_t h0 = pack_bf16x2(o0, o1);
        __nv_bfloat162 hv0 = *reinterpret_cast<__nv_bfloat162*>(&h0);
        uint32_t l0p = pack_bf16x2(o0 - __bfloat162float(hv0.x), o1 - __bfloat162float(hv0.y));
        uint32_t h1 = pack_bf16x2(o2, o3);
        __nv_bfloat162 hv1 = *reinterpret_cast<__nv_bfloat162*>(&h1);
        uint32_t l1p = pack_bf16x2(o2 - __bfloat162float(hv1.x), o3 - __bfloat162float(hv1.y));
        *reinterpret_cast<uint32_t*>(atth + (size_t)row0*2048 + col) = h0;
        *reinterpret_cast<uint32_t*>(attl + (size_t)row0*2048 + col) = l0p;
        *reinterpret_cast<uint32_t*>(atth + (size_t)row1*2048 + col) = h1;
        *reinterpret_cast<uint32_t*>(attl + (size_t)row1*2048 + col) = l1p;
    }
}

// ---------------- host launcher ----------------
extern "C" void kernel_launch(void* const* d_in, const int* in_sizes, int n_in,
                              void* d_out, int out_size)
{
    const float* x      = (const float*)d_in[0];
    const float* wqa    = (const float*)d_in[1];
    const float* wqa_b  = (const float*)d_in[2];
    const float* qnw    = (const float*)d_in[3];
    const float* wqb    = (const float*)d_in[4];
    const float* wqb_b  = (const float*)d_in[5];
    const float* wkva   = (const float*)d_in[6];
    const float* wkva_b = (const float*)d_in[7];
    const float* kvnw   = (const float*)d_in[8];
    const float* wkvb   = (const float*)d_in[9];
    const float* wkvb_b = (const float*)d_in[10];
    const float* wo     = (const float*)d_in[11];
    const float* wo_b   = (const float*)d_in[12];
    float* out = (float*)d_out;

    float *qkv, *bqkv;
    cudaGetSymbolAddress((void**)&qkv, g_qkv);
    cudaGetSymbolAddress((void**)&bqkv, g_bqkv);
    __nv_bfloat16 *xh,*xl,*qah,*qal,*kvch,*kvcl,*atth,*attl;
    __nv_bfloat16 *wqkvh,*wqkvl,*wqbh,*wqbl,*wkvbh,*wkvbl,*woh,*wol;
    __nv_bfloat16 *kfh,*kfl,*vfh,*vfl,*qfh,*qfl;
    cudaGetSymbolAddress((void**)&xh, g_xh);   cudaGetSymbolAddress((void**)&xl, g_xl);
    cudaGetSymbolAddress((void**)&qah, g_qah); cudaGetSymbolAddress((void**)&qal, g_qal);
    cudaGetSymbolAddress((void**)&kvch, g_kvch); cudaGetSymbolAddress((void**)&kvcl, g_kvcl);
    cudaGetSymbolAddress((void**)&atth, g_atth); cudaGetSymbolAddress((void**)&attl, g_attl);
    cudaGetSymbolAddress((void**)&wqkvh, g_wqkvh); cudaGetSymbolAddress((void**)&wqkvl, g_wqkvl);
    cudaGetSymbolAddress((void**)&wqbh, g_wqbh); cudaGetSymbolAddress((void**)&wqbl, g_wqbl);
    cudaGetSymbolAddress((void**)&wkvbh, g_wkvbh); cudaGetSymbolAddress((void**)&wkvbl, g_wkvbl);
    cudaGetSymbolAddress((void**)&woh, g_woh); cudaGetSymbolAddress((void**)&wol, g_wol);
    cudaGetSymbolAddress((void**)&kfh, g_kfh); cudaGetSymbolAddress((void**)&kfl, g_kfl);
    cudaGetSymbolAddress((void**)&vfh, g_vfh); cudaGetSymbolAddress((void**)&vfl, g_vfl);
    cudaGetSymbolAddress((void**)&qfh, g_qfh); cudaGetSymbolAddress((void**)&qfl, g_qfl);

    cudaFuncSetAttribute(flash_mma, cudaFuncAttributeMaxDynamicSharedMemorySize, FL_SMEM + 128);
    cudaFuncSetAttribute(gemm_bf, cudaFuncAttributeMaxDynamicSharedMemorySize, GB_SMEM);
    cudaFuncSetAttribute(gemm_bf_q, cudaFuncAttributeMaxDynamicSharedMemorySize, GB_SMEM);
    cudaFuncSetAttribute(gemm_bf_kv, cudaFuncAttributeMaxDynamicSharedMemorySize, GB_SMEM);

    dim3 t256(256);

    // 1. fused conversions (weights + x + bias combine + rope tables)
    cvt_all<<<CVT_TOTAL, t256>>>(wqa, wkva, wqb, wkvb, wo, x, wqa_b, wkva_b);
    // 2. merged qkv = x @ [wq_a; wkv_a]^T + b
    gemm_bf<<<dim3((QKVW+127)/128, ROWS/128), t256, GB_SMEM>>>(xh, xl, DIMX, wqkvh, wqkvl, DIMX, bqkv, qkv, QKVW, QKVW, DIMX);
    // 3. rmsnorm q + kv_c + k_pe rope (one launch)
    rmsnorm_both<<<dim3(ROWS, 3), t256>>>(qkv, qah, qal, kvch, kvcl, qnw, kvnw, kfh, kfl);
    // 4. q_b GEMM with fused RoPE(table) + scale + bf16 plane epilogue
    gemm_bf_q<<<dim3(3072/128, ROWS/128), t256, GB_SMEM>>>(qah, qal, QLORA, wqbh, wqbl, QLORA, wqb_b, qfh, qfl, 3072, QLORA);
    // 5. kvb GEMM with fused bf16 plane epilogue
    gemm_bf_kv<<<dim3(4096/128, ROWS/128), t256, GB_SMEM>>>(kvch, kvcl, KVLORA, wkvbh, wkvbl, KVLORA, wkvb_b, kfh, kfl, vfh, vfl, 4096, KVLORA);
    // 6. flash (all operands via cp.async bf16 planes)
    flash_mma<<<dim3(SEQL/128, NHEADS, BSZ), t256, FL_SMEM + 128>>>(qfh, qfl, kfh, kfl, vfh, vfl, atth, attl);
    // 7. out
    gemm_bf<<<dim3(2048/128, ROWS/128), t256, GB_SMEM>>>(atth, attl, 2048, woh, wol, 2048, wo_b, out, 2048, 2048, DIMX);
}